// round 5
// baseline (speedup 1.0000x reference)
#include <cuda_runtime.h>
#include <cuda_bf16.h>
#include <math.h>

#define N_NODES 100000
#define N_EDGES 1600000
#define HID 64

// ---------------- scratch (static device memory; no allocations) ----------------
__device__ int   g_deg[N_NODES];
__device__ float g_dinv[N_NODES];
__device__ int   g_rowptr[N_NODES + 1];
__device__ int   g_fill[N_NODES];
__device__ int   g_esrc[N_EDGES];
__device__ int   g_edst[N_EDGES];
__device__ int2  g_csr[N_EDGES];            // .x = src, .y = bits of norm weight
__device__ float g_h1[(size_t)N_NODES * HID];
__device__ float g_h2[(size_t)N_NODES * HID];
__device__ int   g_tilesum[1024];

// ---------------- packed f32x2 helpers (sm_10x packed fp32 pipe) ----------------
__device__ __forceinline__ unsigned long long splat_f32x2(float x) {
    unsigned long long r;
    asm("mov.b64 %0, {%1, %1};" : "=l"(r) : "f"(x));
    return r;
}
__device__ __forceinline__ void fma_f32x2(unsigned long long& d,
                                          unsigned long long a,
                                          unsigned long long b) {
    asm("fma.rn.f32x2 %0, %1, %2, %0;" : "+l"(d) : "l"(a), "l"(b));
}
__device__ __forceinline__ float2 unpack_f32x2(unsigned long long v) {
    float2 f;
    asm("mov.b64 {%0, %1}, %2;" : "=f"(f.x), "=f"(f.y) : "l"(v));
    return f;
}

// ---------------- preprocessing ----------------
__global__ void k_init_deg() {
    int i = blockIdx.x * blockDim.x + threadIdx.x;
    if (i < N_NODES) g_deg[i] = 1;   // self-loop
}

// edge_index arrives as int32
__global__ void k_hist(const int* __restrict__ ei) {
    int e = blockIdx.x * blockDim.x + threadIdx.x;
    if (e < N_EDGES) {
        int s = ei[e];
        int d = ei[N_EDGES + e];
        if ((unsigned)s >= N_NODES) s = 0;
        if ((unsigned)d >= N_NODES) d = 0;
        g_esrc[e] = s;
        g_edst[e] = d;
        atomicAdd(&g_deg[d], 1);
    }
}

#define SCAN_TILES 1024
#define SCAN_TS    98            // 98*1024 >= 100000

// per-tile edge-count sums + fused dinv computation
__global__ void k_scanA() {
    int t = blockIdx.x * blockDim.x + threadIdx.x;
    if (t >= SCAN_TILES) return;
    int start = t * SCAN_TS;
    int end = min(start + SCAN_TS, N_NODES);
    int sum = 0;
    for (int i = start; i < end; i++) {
        int dg = g_deg[i];
        g_dinv[i] = rsqrtf((float)dg);
        sum += dg - 1;
    }
    g_tilesum[t] = sum;
}

// merged scanB+scanC: each of 4 blocks redundantly scans the 1024 tile sums,
// then its 256 threads emit rowptr/fill for their tiles.
__global__ void k_scanBC() {
    __shared__ int ts[SCAN_TILES];
    int tid = threadIdx.x;
    for (int i = tid; i < SCAN_TILES; i += 256) ts[i] = g_tilesum[i];
    __syncthreads();
    if (tid < 32) {
        int lane = tid;
        int s = 0;
#pragma unroll
        for (int k = 0; k < 32; k++) s += ts[lane * 32 + k];
        // exclusive warp scan of 32 chunk sums
        int excl = s;
#pragma unroll
        for (int o = 1; o < 32; o <<= 1) {
            int v = __shfl_up_sync(0xffffffffu, excl, o);
            if (lane >= o) excl += v;
        }
        excl -= s;                     // exclusive prefix of this chunk
        if (lane == 31 && blockIdx.x == 0) g_rowptr[N_NODES] = excl + s;
        int run = excl;
#pragma unroll
        for (int k = 0; k < 32; k++) {
            int tmp = ts[lane * 32 + k];
            ts[lane * 32 + k] = run;
            run += tmp;
        }
    }
    __syncthreads();
    int tile = blockIdx.x * 256 + tid;
    int start = tile * SCAN_TS;
    int end = min(start + SCAN_TS, N_NODES);
    int run = ts[tile];
    for (int i = start; i < end; i++) {
        g_rowptr[i] = run;
        g_fill[i] = run;
        run += g_deg[i] - 1;
    }
}

__global__ void k_scatter() {
    int e = blockIdx.x * blockDim.x + threadIdx.x;
    if (e < N_EDGES) {
        int s = g_esrc[e];
        int d = g_edst[e];
        int pos = atomicAdd(&g_fill[d], 1);
        if ((unsigned)pos < N_EDGES) {
            float w = g_dinv[s] * g_dinv[d];
            g_csr[pos] = make_int2(s, __float_as_int(w));
        }
    }
}

// ---------------- GEMM: g_h1[N,64] = X[N,KDIM] @ W[KDIM,64] ----------------
// Block = 128 threads, one row per thread, 32 packed f32x2 accumulators.
// K in chunks of 32; static smem 24.2 KB:
//   Ws[32][64]  : W chunk, read as 128-bit broadcast (conflict-free)
//   xs[32][129] : x chunk transposed; stride 129 => conflict-free
template <int KDIM, int SRC>
__global__ void k_gemm(const float* __restrict__ Xp, const float* __restrict__ W) {
    __shared__ float Ws[32 * 64];
    __shared__ float xs[32 * 129];
    const float* __restrict__ X = (SRC == 0) ? Xp : (const float*)g_h2;

    int tid = threadIdx.x;
    int base = blockIdx.x * 128;

    unsigned long long acc[32];   // 32 x (2 packed fp32) = 64 output cols
#pragma unroll
    for (int c = 0; c < 32; c++) acc[c] = 0ull;

    for (int k0 = 0; k0 < KDIM; k0 += 32) {
        __syncthreads();   // previous chunk fully consumed
#pragma unroll
        for (int it = 0; it < 4; it++) {
            int idx = tid + 128 * it;
            ((float4*)Ws)[idx] = ((const float4*)W)[k0 * 16 + idx];
        }
#pragma unroll
        for (int it = 0; it < 8; it++) {
            int idx = tid + 128 * it;          // 0..1023
            int r = idx >> 3;                  // 0..127
            int u4 = idx & 7;                  // 0..7
            float4 v = make_float4(0.f, 0.f, 0.f, 0.f);
            int grow = base + r;
            if (grow < N_NODES)
                v = *(const float4*)&X[(size_t)grow * KDIM + k0 + u4 * 4];
            xs[(u4 * 4 + 0) * 129 + r] = v.x;
            xs[(u4 * 4 + 1) * 129 + r] = v.y;
            xs[(u4 * 4 + 2) * 129 + r] = v.z;
            xs[(u4 * 4 + 3) * 129 + r] = v.w;
        }
        __syncthreads();
#pragma unroll 4
        for (int u = 0; u < 32; u++) {
            unsigned long long xv = splat_f32x2(xs[u * 129 + tid]);
            const ulonglong2* Wr = (const ulonglong2*)&Ws[u * 64];
#pragma unroll
            for (int cc = 0; cc < 16; cc++) {
                ulonglong2 wv = Wr[cc];        // 128-bit broadcast load
                fma_f32x2(acc[cc * 2 + 0], xv, wv.x);
                fma_f32x2(acc[cc * 2 + 1], xv, wv.y);
            }
        }
    }
    int row = base + tid;
    if (row < N_NODES) {
        float4* o = (float4*)&g_h1[(size_t)row * 64];
#pragma unroll
        for (int cc = 0; cc < 16; cc++) {
            float2 lo = unpack_f32x2(acc[cc * 2 + 0]);
            float2 hi = unpack_f32x2(acc[cc * 2 + 1]);
            o[cc] = make_float4(lo.x, lo.y, hi.x, hi.y);
        }
    }
}

// ---------------- Aggregation + epilogue: warp per node ----------------
// OUT[i] = sum_{e: dst=i} w_e * g_h1[src_e] + dinv[i]^2 * g_h1[i] + bias
// MODE=1: relu + L2-normalize, writes g_h2.  MODE=0: plain, writes OUTp.
template <int MODE>
__global__ void k_agg(const float* __restrict__ bias, float* __restrict__ OUTp) {
    int gwarp = (blockIdx.x * blockDim.x + threadIdx.x) >> 5;
    int lane = threadIdx.x & 31;
    if (gwarp >= N_NODES) return;
    int i = gwarp;

    float di = g_dinv[i];
    int beg = g_rowptr[i];
    int end = g_rowptr[i + 1];

    const float2* __restrict__ H2 = (const float2*)g_h1;
    float2 hv = H2[(size_t)i * 32 + lane];
    float wself = di * di;
    float a0 = wself * hv.x;
    float a1 = wself * hv.y;

    for (int j = beg; j < end; j++) {
        int2 sw = g_csr[j];                    // uniform across warp
        float w = __int_as_float(sw.y);
        float2 hs = H2[(size_t)sw.x * 32 + lane];
        a0 += w * hs.x;
        a1 += w * hs.y;
    }

    float2 b = ((const float2*)bias)[lane];
    a0 += b.x;
    a1 += b.y;

    if (MODE == 1) {
        a0 = fmaxf(a0, 0.f);
        a1 = fmaxf(a1, 0.f);
        float ss = a0 * a0 + a1 * a1;
#pragma unroll
        for (int o = 16; o; o >>= 1) ss += __shfl_xor_sync(0xffffffffu, ss, o);
        float inv = 1.f / fmaxf(sqrtf(ss), 1e-12f);
        a0 *= inv;
        a1 *= inv;
        ((float2*)g_h2)[(size_t)i * 32 + lane] = make_float2(a0, a1);
    } else {
        ((float2*)OUTp)[(size_t)i * 32 + lane] = make_float2(a0, a1);
    }
}

// ---------------- launch ----------------
extern "C" void kernel_launch(void* const* d_in, const int* in_sizes, int n_in,
                              void* d_out, int out_size) {
    const float* x = (const float*)d_in[0];
    const int* ei = (const int*)d_in[1];     // int32 edge_index [2, E]
    const float* W1 = (const float*)d_in[2];
    const float* b1 = (const float*)d_in[3];
    const float* W2 = (const float*)d_in[4];
    const float* b2 = (const float*)d_in[5];
    const float* W3 = (const float*)d_in[6];
    const float* b3 = (const float*)d_in[7];
    float* out = (float*)d_out;

    const int T = 256;
    // graph preprocessing (5 launches; rebuilt every replay)
    k_init_deg<<<(N_NODES + T - 1) / T, T>>>();
    k_hist<<<(N_EDGES + T - 1) / T, T>>>(ei);
    k_scanA<<<4, 256>>>();
    k_scanBC<<<4, 256>>>();
    k_scatter<<<(N_EDGES + T - 1) / T, T>>>();

    int gemm_grid = (N_NODES + 127) / 128;
    int agg_grid = (N_NODES * 32 + T - 1) / T;

    // layer 1 (gemm1 is launch #6 -> lands under ncu -s 5 -c 1)
    k_gemm<256, 0><<<gemm_grid, 128>>>(x, W1);
    k_agg<1><<<agg_grid, T>>>(b1, nullptr);
    // layer 2
    k_gemm<64, 1><<<gemm_grid, 128>>>(nullptr, W2);
    k_agg<1><<<agg_grid, T>>>(b2, nullptr);
    // layer 3
    k_gemm<64, 1><<<gemm_grid, 128>>>(nullptr, W3);
    k_agg<0><<<agg_grid, T>>>(b3, out);
}

// round 6
// speedup vs baseline: 1.0863x; 1.0863x over previous
#include <cuda_runtime.h>
#include <cuda_bf16.h>
#include <math.h>

#define N_NODES 100000
#define N_EDGES 1600000
#define HID 64
#define SCAN_BLOCKS ((N_NODES + 255) / 256)   // 391

// ---------------- scratch (static device memory; no allocations) ----------------
__device__ int   g_deg[N_NODES];
__device__ float g_dinv[N_NODES];
__device__ int   g_rowptr[N_NODES + 1];
__device__ int   g_fill[N_NODES];
__device__ int   g_esrc[N_EDGES];
__device__ int   g_edst[N_EDGES];
__device__ int2  g_csr[N_EDGES];            // .x = src, .y = bits of norm weight
__device__ float g_h1[(size_t)N_NODES * HID];
__device__ float g_h2[(size_t)N_NODES * HID];
__device__ int   g_blocksum[SCAN_BLOCKS];
__device__ int   g_blockoff[SCAN_BLOCKS];

// ---------------- preprocessing ----------------
__global__ void k_init_deg() {
    int i = blockIdx.x * blockDim.x + threadIdx.x;
    if (i < N_NODES) g_deg[i] = 1;   // self-loop
}

// edge_index arrives as int32
__global__ void k_hist(const int* __restrict__ ei) {
    int e = blockIdx.x * blockDim.x + threadIdx.x;
    if (e < N_EDGES) {
        int s = ei[e];
        int d = ei[N_EDGES + e];
        if ((unsigned)s >= N_NODES) s = 0;
        if ((unsigned)d >= N_NODES) d = 0;
        g_esrc[e] = s;
        g_edst[e] = d;
        atomicAdd(&g_deg[d], 1);
    }
}

// block-level exclusive scan of (deg-1); also computes dinv. 391 blocks x 256.
__global__ void k_blockscan() {
    __shared__ int wsum[8];
    int tid = threadIdx.x;
    int lane = tid & 31;
    int wid = tid >> 5;
    int i = blockIdx.x * 256 + tid;

    int e = 0;
    if (i < N_NODES) {
        int dg = g_deg[i];
        g_dinv[i] = rsqrtf((float)dg);
        e = dg - 1;
    }
    // inclusive warp scan
    int incl = e;
#pragma unroll
    for (int o = 1; o < 32; o <<= 1) {
        int v = __shfl_up_sync(0xffffffffu, incl, o);
        if (lane >= o) incl += v;
    }
    if (lane == 31) wsum[wid] = incl;
    __syncthreads();
    if (wid == 0) {
        int v = (lane < 8) ? wsum[lane] : 0;
        int s = v;
#pragma unroll
        for (int o = 1; o < 8; o <<= 1) {
            int u = __shfl_up_sync(0xffffffffu, s, o);
            if (lane >= o) s += u;
        }
        if (lane < 8) wsum[lane] = s - v;     // exclusive warp offsets
    }
    __syncthreads();
    int excl = incl - e + wsum[wid];
    if (i < N_NODES) g_rowptr[i] = excl;       // partial (block-local)
    if (tid == 255) g_blocksum[blockIdx.x] = excl + e;
}

// 1 block, 512 threads: exclusive scan of 391 block sums.
__global__ void k_scanmid() {
    __shared__ int wsum[16];
    int tid = threadIdx.x;
    int lane = tid & 31;
    int wid = tid >> 5;
    int v = (tid < SCAN_BLOCKS) ? g_blocksum[tid] : 0;
    int incl = v;
#pragma unroll
    for (int o = 1; o < 32; o <<= 1) {
        int u = __shfl_up_sync(0xffffffffu, incl, o);
        if (lane >= o) incl += u;
    }
    if (lane == 31) wsum[wid] = incl;
    __syncthreads();
    if (wid == 0) {
        int w = (lane < 16) ? wsum[lane] : 0;
        int s = w;
#pragma unroll
        for (int o = 1; o < 16; o <<= 1) {
            int u = __shfl_up_sync(0xffffffffu, s, o);
            if (lane >= o) s += u;
        }
        if (lane < 16) wsum[lane] = s - w;
    }
    __syncthreads();
    int excl = incl - v + wsum[wid];
    if (tid < SCAN_BLOCKS) g_blockoff[tid] = excl;
    if (tid == SCAN_BLOCKS - 1) g_rowptr[N_NODES] = excl + v;
}

__global__ void k_addoff() {
    int i = blockIdx.x * blockDim.x + threadIdx.x;
    if (i < N_NODES) {
        int v = g_rowptr[i] + g_blockoff[blockIdx.x * 256 / 256 * 256 / 256 == 0 ? 0 : 0];
        // (the above is wrong-proof: compute block index directly)
        v = g_rowptr[i] + g_blockoff[i >> 8];
        g_rowptr[i] = v;
        g_fill[i] = v;
    }
}

__global__ void k_scatter() {
    int e = blockIdx.x * blockDim.x + threadIdx.x;
    if (e < N_EDGES) {
        int s = g_esrc[e];
        int d = g_edst[e];
        int pos = atomicAdd(&g_fill[d], 1);
        if ((unsigned)pos < N_EDGES) {
            float w = g_dinv[s] * g_dinv[d];
            g_csr[pos] = make_int2(s, __float_as_int(w));
        }
    }
}

// ---------------- GEMM: g_h1[N,64] = X[N,KDIM] @ W[KDIM,64] ----------------
// Block = 128 threads, one row per thread, 64 fp32 accumulators.
// K in chunks of 32; static smem 24.2 KB:
//   Ws[32][64]  : W chunk, read as float4 broadcast (conflict-free)
//   xs[32][129] : x chunk transposed; stride 129 => conflict-free
template <int KDIM, int SRC>
__global__ void k_gemm(const float* __restrict__ Xp, const float* __restrict__ W) {
    __shared__ float Ws[32 * 64];
    __shared__ float xs[32 * 129];
    const float* __restrict__ X = (SRC == 0) ? Xp : (const float*)g_h2;

    int tid = threadIdx.x;
    int base = blockIdx.x * 128;

    float acc[64];
#pragma unroll
    for (int c = 0; c < 64; c++) acc[c] = 0.f;

    for (int k0 = 0; k0 < KDIM; k0 += 32) {
        __syncthreads();   // previous chunk fully consumed
#pragma unroll
        for (int it = 0; it < 4; it++) {
            int idx = tid + 128 * it;
            ((float4*)Ws)[idx] = ((const float4*)W)[k0 * 16 + idx];
        }
#pragma unroll
        for (int it = 0; it < 8; it++) {
            int idx = tid + 128 * it;          // 0..1023
            int r = idx >> 3;                  // 0..127
            int u4 = idx & 7;                  // 0..7
            float4 v = make_float4(0.f, 0.f, 0.f, 0.f);
            int grow = base + r;
            if (grow < N_NODES)
                v = *(const float4*)&X[(size_t)grow * KDIM + k0 + u4 * 4];
            xs[(u4 * 4 + 0) * 129 + r] = v.x;
            xs[(u4 * 4 + 1) * 129 + r] = v.y;
            xs[(u4 * 4 + 2) * 129 + r] = v.z;
            xs[(u4 * 4 + 3) * 129 + r] = v.w;
        }
        __syncthreads();
#pragma unroll 4
        for (int u = 0; u < 32; u++) {
            float xv = xs[u * 129 + tid];
            const float4* Wr = (const float4*)&Ws[u * 64];
#pragma unroll
            for (int cc = 0; cc < 16; cc++) {
                float4 wv = Wr[cc];
                acc[cc * 4 + 0] += xv * wv.x;
                acc[cc * 4 + 1] += xv * wv.y;
                acc[cc * 4 + 2] += xv * wv.z;
                acc[cc * 4 + 3] += xv * wv.w;
            }
        }
    }
    int row = base + tid;
    if (row < N_NODES) {
        float4* o = (float4*)&g_h1[(size_t)row * 64];
#pragma unroll
        for (int cc = 0; cc < 16; cc++)
            o[cc] = make_float4(acc[cc * 4 + 0], acc[cc * 4 + 1],
                                acc[cc * 4 + 2], acc[cc * 4 + 3]);
    }
}

// ---------------- Aggregation + epilogue: warp per node ----------------
// OUT[i] = sum_{e: dst=i} w_e * g_h1[src_e] + dinv[i]^2 * g_h1[i] + bias
// MODE=1: relu + L2-normalize, writes g_h2.  MODE=0: plain, writes OUTp.
template <int MODE>
__global__ void k_agg(const float* __restrict__ bias, float* __restrict__ OUTp) {
    int gwarp = (blockIdx.x * blockDim.x + threadIdx.x) >> 5;
    int lane = threadIdx.x & 31;
    if (gwarp >= N_NODES) return;
    int i = gwarp;

    float di = g_dinv[i];
    int beg = g_rowptr[i];
    int end = g_rowptr[i + 1];

    const float2* __restrict__ H2 = (const float2*)g_h1;
    float2 hv = H2[(size_t)i * 32 + lane];
    float wself = di * di;
    float a0 = wself * hv.x;
    float a1 = wself * hv.y;

    // 4-wide unrolled edge loop: batch 4 edge records + 4 gathers for MLP
    int j = beg;
    for (; j + 4 <= end; j += 4) {
        int2 e0 = g_csr[j + 0];
        int2 e1 = g_csr[j + 1];
        int2 e2 = g_csr[j + 2];
        int2 e3 = g_csr[j + 3];
        float2 h0 = H2[(size_t)e0.x * 32 + lane];
        float2 h1v = H2[(size_t)e1.x * 32 + lane];
        float2 h2v = H2[(size_t)e2.x * 32 + lane];
        float2 h3 = H2[(size_t)e3.x * 32 + lane];
        a0 += __int_as_float(e0.y) * h0.x;  a1 += __int_as_float(e0.y) * h0.y;
        a0 += __int_as_float(e1.y) * h1v.x; a1 += __int_as_float(e1.y) * h1v.y;
        a0 += __int_as_float(e2.y) * h2v.x; a1 += __int_as_float(e2.y) * h2v.y;
        a0 += __int_as_float(e3.y) * h3.x;  a1 += __int_as_float(e3.y) * h3.y;
    }
    for (; j < end; j++) {
        int2 sw = g_csr[j];
        float w = __int_as_float(sw.y);
        float2 hs = H2[(size_t)sw.x * 32 + lane];
        a0 += w * hs.x;
        a1 += w * hs.y;
    }

    float2 b = ((const float2*)bias)[lane];
    a0 += b.x;
    a1 += b.y;

    if (MODE == 1) {
        a0 = fmaxf(a0, 0.f);
        a1 = fmaxf(a1, 0.f);
        float ss = a0 * a0 + a1 * a1;
#pragma unroll
        for (int o = 16; o; o >>= 1) ss += __shfl_xor_sync(0xffffffffu, ss, o);
        float inv = 1.f / fmaxf(sqrtf(ss), 1e-12f);
        a0 *= inv;
        a1 *= inv;
        ((float2*)g_h2)[(size_t)i * 32 + lane] = make_float2(a0, a1);
    } else {
        ((float2*)OUTp)[(size_t)i * 32 + lane] = make_float2(a0, a1);
    }
}

// ---------------- launch ----------------
extern "C" void kernel_launch(void* const* d_in, const int* in_sizes, int n_in,
                              void* d_out, int out_size) {
    const float* x = (const float*)d_in[0];
    const int* ei = (const int*)d_in[1];     // int32 edge_index [2, E]
    const float* W1 = (const float*)d_in[2];
    const float* b1 = (const float*)d_in[3];
    const float* W2 = (const float*)d_in[4];
    const float* b2 = (const float*)d_in[5];
    const float* W3 = (const float*)d_in[6];
    const float* b3 = (const float*)d_in[7];
    float* out = (float*)d_out;

    const int T = 256;
    int gemm_grid = (N_NODES + 127) / 128;
    int agg_grid = (N_NODES * 32 + T - 1) / T;

    // preprocessing (parallel scan) with gemm1 hoisted to launch index 3
    // (capture lands on index 3 -> profiles the big GEMM next round)
    k_init_deg<<<SCAN_BLOCKS, T>>>();                       // 0
    k_hist<<<(N_EDGES + T - 1) / T, T>>>(ei);               // 1
    k_blockscan<<<SCAN_BLOCKS, T>>>();                      // 2
    k_gemm<256, 0><<<gemm_grid, 128>>>(x, W1);              // 3  <- profiled
    k_scanmid<<<1, 512>>>();                                // 4
    k_addoff<<<SCAN_BLOCKS, T>>>();                         // 5
    k_scatter<<<(N_EDGES + T - 1) / T, T>>>();              // 6

    // layer 1 aggregation
    k_agg<1><<<agg_grid, T>>>(b1, nullptr);                 // 7
    // layer 2
    k_gemm<64, 1><<<gemm_grid, 128>>>(nullptr, W2);         // 8
    k_agg<1><<<agg_grid, T>>>(b2, nullptr);                 // 9
    // layer 3
    k_gemm<64, 1><<<gemm_grid, 128>>>(nullptr, W3);         // 10
    k_agg<0><<<agg_grid, T>>>(b3, out);                     // 11
}

// round 7
// speedup vs baseline: 1.2001x; 1.1047x over previous
#include <cuda_runtime.h>
#include <cuda_bf16.h>
#include <math.h>

#define N_NODES 100000
#define N_EDGES 1600000
#define HID 64
#define SCAN_BLOCKS ((N_NODES + 255) / 256)   // 391

// ---------------- scratch (static device memory; no allocations) ----------------
__device__ int   g_deg[N_NODES];
__device__ float g_dinv[N_NODES];
__device__ int   g_rowptr[N_NODES + 1];
__device__ int   g_fill[N_NODES];
__device__ int   g_esrc[N_EDGES];
__device__ int   g_edst[N_EDGES];
__device__ int2  g_csr[N_EDGES];            // .x = src, .y = bits of norm weight
__device__ float g_h1[(size_t)N_NODES * HID];
__device__ float g_h2[(size_t)N_NODES * HID];
__device__ int   g_blocksum[SCAN_BLOCKS];
__device__ int   g_blockoff[SCAN_BLOCKS];

// ---------------- preprocessing ----------------
__global__ void k_init_deg() {
    int i = blockIdx.x * blockDim.x + threadIdx.x;
    if (i < N_NODES) g_deg[i] = 1;   // self-loop
}

__global__ void k_hist(const int* __restrict__ ei) {
    int e = blockIdx.x * blockDim.x + threadIdx.x;
    if (e < N_EDGES) {
        int s = ei[e];
        int d = ei[N_EDGES + e];
        if ((unsigned)s >= N_NODES) s = 0;
        if ((unsigned)d >= N_NODES) d = 0;
        g_esrc[e] = s;
        g_edst[e] = d;
        atomicAdd(&g_deg[d], 1);
    }
}

// block-level exclusive scan of (deg-1); also computes dinv. 391 blocks x 256.
__global__ void k_blockscan() {
    __shared__ int wsum[8];
    int tid = threadIdx.x;
    int lane = tid & 31;
    int wid = tid >> 5;
    int i = blockIdx.x * 256 + tid;

    int e = 0;
    if (i < N_NODES) {
        int dg = g_deg[i];
        g_dinv[i] = rsqrtf((float)dg);
        e = dg - 1;
    }
    int incl = e;
#pragma unroll
    for (int o = 1; o < 32; o <<= 1) {
        int v = __shfl_up_sync(0xffffffffu, incl, o);
        if (lane >= o) incl += v;
    }
    if (lane == 31) wsum[wid] = incl;
    __syncthreads();
    if (wid == 0) {
        int v = (lane < 8) ? wsum[lane] : 0;
        int s = v;
#pragma unroll
        for (int o = 1; o < 8; o <<= 1) {
            int u = __shfl_up_sync(0xffffffffu, s, o);
            if (lane >= o) s += u;
        }
        if (lane < 8) wsum[lane] = s - v;
    }
    __syncthreads();
    int excl = incl - e + wsum[wid];
    if (i < N_NODES) g_rowptr[i] = excl;       // partial (block-local)
    if (tid == 255) g_blocksum[blockIdx.x] = excl + e;
}

// 1 block, 512 threads: exclusive scan of 391 block sums.
__global__ void k_scanmid() {
    __shared__ int wsum[16];
    int tid = threadIdx.x;
    int lane = tid & 31;
    int wid = tid >> 5;
    int v = (tid < SCAN_BLOCKS) ? g_blocksum[tid] : 0;
    int incl = v;
#pragma unroll
    for (int o = 1; o < 32; o <<= 1) {
        int u = __shfl_up_sync(0xffffffffu, incl, o);
        if (lane >= o) incl += u;
    }
    if (lane == 31) wsum[wid] = incl;
    __syncthreads();
    if (wid == 0) {
        int w = (lane < 16) ? wsum[lane] : 0;
        int s = w;
#pragma unroll
        for (int o = 1; o < 16; o <<= 1) {
            int u = __shfl_up_sync(0xffffffffu, s, o);
            if (lane >= o) s += u;
        }
        if (lane < 16) wsum[lane] = s - w;
    }
    __syncthreads();
    int excl = incl - v + wsum[wid];
    if (tid < SCAN_BLOCKS) g_blockoff[tid] = excl;
    if (tid == SCAN_BLOCKS - 1) g_rowptr[N_NODES] = excl + v;
}

__global__ void k_addoff() {
    int i = blockIdx.x * blockDim.x + threadIdx.x;
    if (i < N_NODES) {
        int v = g_rowptr[i] + g_blockoff[i >> 8];
        g_rowptr[i] = v;
        g_fill[i] = v;
    }
}

__global__ void k_scatter() {
    int e = blockIdx.x * blockDim.x + threadIdx.x;
    if (e < N_EDGES) {
        int s = g_esrc[e];
        int d = g_edst[e];
        int pos = atomicAdd(&g_fill[d], 1);
        if ((unsigned)pos < N_EDGES) {
            float w = g_dinv[s] * g_dinv[d];
            g_csr[pos] = make_int2(s, __float_as_int(w));
        }
    }
}

// ---------------- GEMM: g_h1[N,64] = X[N,KDIM] @ W[KDIM,64] ----------------
// 2-D register-tiled SGEMM. 512 threads/block, tile 128(M) x 64(N), BK=32.
// Each thread computes a 4x4 micro-tile: per k, 1 LDS.128 (A) + 1 LDS.128 (B)
// feed 16 FMA (LDS:FMA = 1:8). ~45 regs -> 3 blocks/SM (~75% occ).
// A smem [k][m] with XOR swizzle: phys_f4(k,m4) = k*32 + (m4 ^ k)
//   - compute loads: 16B-aligned, 8 distinct granules/warp -> conflict-free
//   - transpose staging stores: banks 4*((r>>2)^k) + (r&3) all distinct
// B smem [k][n] row-major direct copy (no transpose).
template <int KDIM, int SRC>
__global__ void k_gemm(const float* __restrict__ Xp, const float* __restrict__ W) {
    __shared__ float As[32 * 128];   // 16 KB, swizzled [k][m]
    __shared__ float Bs[32 * 64];    // 8 KB,  [k][n]
    const float* __restrict__ X = (SRC == 0) ? Xp : (const float*)g_h2;

    int tid = threadIdx.x;
    int base = blockIdx.x * 128;

    // warp-tiled thread map: m_idx in [0,32), n_idx in [0,16)
    int lane = tid & 31;
    int w = tid >> 5;                    // warp id [0,16)
    int m_idx = (w & 3) * 8 + (lane & 7);
    int n_idx = (w >> 2) * 4 + (lane >> 3);

    float acc[4][4];
#pragma unroll
    for (int i = 0; i < 4; i++)
#pragma unroll
        for (int j = 0; j < 4; j++) acc[i][j] = 0.f;

    for (int k0 = 0; k0 < KDIM; k0 += 32) {
        __syncthreads();   // previous chunk fully consumed
        // stage A: X chunk [128 rows][32 k] = 1024 float4, 2 per thread,
        // transposed+swizzled scalar stores (conflict-free, see header)
#pragma unroll
        for (int it = 0; it < 2; it++) {
            int idx = tid + 512 * it;      // 0..1023
            int r = idx >> 3;              // row 0..127
            int u4 = idx & 7;              // k-quad 0..7
            float4 v = make_float4(0.f, 0.f, 0.f, 0.f);
            int grow = base + r;
            if (grow < N_NODES)
                v = *(const float4*)&X[(size_t)grow * KDIM + k0 + u4 * 4];
            int m4 = r >> 2, c2 = r & 3;
            int kk = u4 * 4;
            As[((kk + 0) * 32 + (m4 ^ (kk + 0))) * 4 + c2] = v.x;
            As[((kk + 1) * 32 + (m4 ^ (kk + 1))) * 4 + c2] = v.y;
            As[((kk + 2) * 32 + (m4 ^ (kk + 2))) * 4 + c2] = v.z;
            As[((kk + 3) * 32 + (m4 ^ (kk + 3))) * 4 + c2] = v.w;
        }
        // stage B: W chunk [32][64] = 512 float4, 1 per thread
        {
            int k = tid >> 4;
            int n4 = tid & 15;
            *(float4*)&Bs[k * 64 + n4 * 4] =
                *(const float4*)&W[(size_t)(k0 + k) * 64 + n4 * 4];
        }
        __syncthreads();

#pragma unroll 8
        for (int k = 0; k < 32; k++) {
            float4 a = *(const float4*)&As[(k * 32 + (m_idx ^ k)) * 4];
            float4 b = *(const float4*)&Bs[k * 64 + n_idx * 4];
            acc[0][0] += a.x * b.x; acc[0][1] += a.x * b.y;
            acc[0][2] += a.x * b.z; acc[0][3] += a.x * b.w;
            acc[1][0] += a.y * b.x; acc[1][1] += a.y * b.y;
            acc[1][2] += a.y * b.z; acc[1][3] += a.y * b.w;
            acc[2][0] += a.z * b.x; acc[2][1] += a.z * b.y;
            acc[2][2] += a.z * b.z; acc[2][3] += a.z * b.w;
            acc[3][0] += a.w * b.x; acc[3][1] += a.w * b.y;
            acc[3][2] += a.w * b.z; acc[3][3] += a.w * b.w;
        }
    }

#pragma unroll
    for (int i = 0; i < 4; i++) {
        int row = base + m_idx * 4 + i;
        if (row < N_NODES)
            *(float4*)&g_h1[(size_t)row * 64 + n_idx * 4] =
                make_float4(acc[i][0], acc[i][1], acc[i][2], acc[i][3]);
    }
}

// ---------------- Aggregation + epilogue: warp per node ----------------
template <int MODE>
__global__ void k_agg(const float* __restrict__ bias, float* __restrict__ OUTp) {
    int gwarp = (blockIdx.x * blockDim.x + threadIdx.x) >> 5;
    int lane = threadIdx.x & 31;
    if (gwarp >= N_NODES) return;
    int i = gwarp;

    float di = g_dinv[i];
    int beg = g_rowptr[i];
    int end = g_rowptr[i + 1];

    const float2* __restrict__ H2 = (const float2*)g_h1;
    float2 hv = H2[(size_t)i * 32 + lane];
    float wself = di * di;
    float a0 = wself * hv.x;
    float a1 = wself * hv.y;

    int j = beg;
    for (; j + 4 <= end; j += 4) {
        int2 e0 = g_csr[j + 0];
        int2 e1 = g_csr[j + 1];
        int2 e2 = g_csr[j + 2];
        int2 e3 = g_csr[j + 3];
        float2 h0 = H2[(size_t)e0.x * 32 + lane];
        float2 h1v = H2[(size_t)e1.x * 32 + lane];
        float2 h2v = H2[(size_t)e2.x * 32 + lane];
        float2 h3 = H2[(size_t)e3.x * 32 + lane];
        a0 += __int_as_float(e0.y) * h0.x;  a1 += __int_as_float(e0.y) * h0.y;
        a0 += __int_as_float(e1.y) * h1v.x; a1 += __int_as_float(e1.y) * h1v.y;
        a0 += __int_as_float(e2.y) * h2v.x; a1 += __int_as_float(e2.y) * h2v.y;
        a0 += __int_as_float(e3.y) * h3.x;  a1 += __int_as_float(e3.y) * h3.y;
    }
    for (; j < end; j++) {
        int2 sw = g_csr[j];
        float w = __int_as_float(sw.y);
        float2 hs = H2[(size_t)sw.x * 32 + lane];
        a0 += w * hs.x;
        a1 += w * hs.y;
    }

    float2 b = ((const float2*)bias)[lane];
    a0 += b.x;
    a1 += b.y;

    if (MODE == 1) {
        a0 = fmaxf(a0, 0.f);
        a1 = fmaxf(a1, 0.f);
        float ss = a0 * a0 + a1 * a1;
#pragma unroll
        for (int o = 16; o; o >>= 1) ss += __shfl_xor_sync(0xffffffffu, ss, o);
        float inv = 1.f / fmaxf(sqrtf(ss), 1e-12f);
        a0 *= inv;
        a1 *= inv;
        ((float2*)g_h2)[(size_t)i * 32 + lane] = make_float2(a0, a1);
    } else {
        ((float2*)OUTp)[(size_t)i * 32 + lane] = make_float2(a0, a1);
    }
}

// ---------------- launch ----------------
extern "C" void kernel_launch(void* const* d_in, const int* in_sizes, int n_in,
                              void* d_out, int out_size) {
    const float* x = (const float*)d_in[0];
    const int* ei = (const int*)d_in[1];     // int32 edge_index [2, E]
    const float* W1 = (const float*)d_in[2];
    const float* b1 = (const float*)d_in[3];
    const float* W2 = (const float*)d_in[4];
    const float* b2 = (const float*)d_in[5];
    const float* W3 = (const float*)d_in[6];
    const float* b3 = (const float*)d_in[7];
    float* out = (float*)d_out;

    const int T = 256;
    int gemm_grid = (N_NODES + 127) / 128;
    int agg_grid = (N_NODES * 32 + T - 1) / T;

    // preprocessing with gemm1 at launch index 3 (ncu capture target)
    k_init_deg<<<SCAN_BLOCKS, T>>>();                       // 0
    k_hist<<<(N_EDGES + T - 1) / T, T>>>(ei);               // 1
    k_blockscan<<<SCAN_BLOCKS, T>>>();                      // 2
    k_gemm<256, 0><<<gemm_grid, 512>>>(x, W1);              // 3  <- profiled
    k_scanmid<<<1, 512>>>();                                // 4
    k_addoff<<<SCAN_BLOCKS, T>>>();                         // 5
    k_scatter<<<(N_EDGES + T - 1) / T, T>>>();              // 6

    // layer 1 aggregation
    k_agg<1><<<agg_grid, T>>>(b1, nullptr);                 // 7
    // layer 2
    k_gemm<64, 1><<<gemm_grid, 512>>>(nullptr, W2);         // 8
    k_agg<1><<<agg_grid, T>>>(b2, nullptr);                 // 9
    // layer 3
    k_gemm<64, 1><<<gemm_grid, 512>>>(nullptr, W3);         // 10
    k_agg<0><<<agg_grid, T>>>(b3, out);                     // 11
}

// round 8
// speedup vs baseline: 1.2551x; 1.0458x over previous
#include <cuda_runtime.h>
#include <cuda_bf16.h>
#include <math.h>

#define N_NODES 100000
#define N_EDGES 1600000
#define HID 64
#define SCAN_BLOCKS ((N_NODES + 255) / 256)   // 391

// ---------------- scratch (static device memory; no allocations) ----------------
__device__ int   g_deg[N_NODES];
__device__ float g_dinv[N_NODES];
__device__ int   g_rowptr[N_NODES + 1];
__device__ int   g_fill[N_NODES];
__device__ int   g_esrc[N_EDGES];
__device__ int   g_edst[N_EDGES];
__device__ int2  g_csr[N_EDGES];            // .x = src, .y = bits of norm weight
__device__ float g_h1[(size_t)N_NODES * HID];
__device__ float g_h2[(size_t)N_NODES * HID];
__device__ int   g_blocksum[SCAN_BLOCKS];
__device__ int   g_blockoff[SCAN_BLOCKS];

// ---------------- packed f32x2 helpers ----------------
__device__ __forceinline__ unsigned long long splat_f32x2(float x) {
    unsigned long long r;
    asm("mov.b64 %0, {%1, %1};" : "=l"(r) : "f"(x));
    return r;
}
__device__ __forceinline__ void fma_f32x2(unsigned long long& d,
                                          unsigned long long a,
                                          unsigned long long b) {
    asm("fma.rn.f32x2 %0, %1, %2, %0;" : "+l"(d) : "l"(a), "l"(b));
}
__device__ __forceinline__ float2 unpack_f32x2(unsigned long long v) {
    float2 f;
    asm("mov.b64 {%0, %1}, %2;" : "=f"(f.x), "=f"(f.y) : "l"(v));
    return f;
}

// ---------------- preprocessing ----------------
__global__ void k_init_deg() {
    int i = blockIdx.x * blockDim.x + threadIdx.x;
    if (i < N_NODES) g_deg[i] = 1;   // self-loop
}

__global__ void k_hist(const int* __restrict__ ei) {
    int e = blockIdx.x * blockDim.x + threadIdx.x;
    if (e < N_EDGES) {
        int s = ei[e];
        int d = ei[N_EDGES + e];
        if ((unsigned)s >= N_NODES) s = 0;
        if ((unsigned)d >= N_NODES) d = 0;
        g_esrc[e] = s;
        g_edst[e] = d;
        atomicAdd(&g_deg[d], 1);
    }
}

// block-level exclusive scan of (deg-1); also computes dinv. 391 blocks x 256.
__global__ void k_blockscan() {
    __shared__ int wsum[8];
    int tid = threadIdx.x;
    int lane = tid & 31;
    int wid = tid >> 5;
    int i = blockIdx.x * 256 + tid;

    int e = 0;
    if (i < N_NODES) {
        int dg = g_deg[i];
        g_dinv[i] = rsqrtf((float)dg);
        e = dg - 1;
    }
    int incl = e;
#pragma unroll
    for (int o = 1; o < 32; o <<= 1) {
        int v = __shfl_up_sync(0xffffffffu, incl, o);
        if (lane >= o) incl += v;
    }
    if (lane == 31) wsum[wid] = incl;
    __syncthreads();
    if (wid == 0) {
        int v = (lane < 8) ? wsum[lane] : 0;
        int s = v;
#pragma unroll
        for (int o = 1; o < 8; o <<= 1) {
            int u = __shfl_up_sync(0xffffffffu, s, o);
            if (lane >= o) s += u;
        }
        if (lane < 8) wsum[lane] = s - v;
    }
    __syncthreads();
    int excl = incl - e + wsum[wid];
    if (i < N_NODES) g_rowptr[i] = excl;       // partial (block-local)
    if (tid == 255) g_blocksum[blockIdx.x] = excl + e;
}

// 1 block, 512 threads: exclusive scan of 391 block sums.
__global__ void k_scanmid() {
    __shared__ int wsum[16];
    int tid = threadIdx.x;
    int lane = tid & 31;
    int wid = tid >> 5;
    int v = (tid < SCAN_BLOCKS) ? g_blocksum[tid] : 0;
    int incl = v;
#pragma unroll
    for (int o = 1; o < 32; o <<= 1) {
        int u = __shfl_up_sync(0xffffffffu, incl, o);
        if (lane >= o) incl += u;
    }
    if (lane == 31) wsum[wid] = incl;
    __syncthreads();
    if (wid == 0) {
        int w = (lane < 16) ? wsum[lane] : 0;
        int s = w;
#pragma unroll
        for (int o = 1; o < 16; o <<= 1) {
            int u = __shfl_up_sync(0xffffffffu, s, o);
            if (lane >= o) s += u;
        }
        if (lane < 16) wsum[lane] = s - w;
    }
    __syncthreads();
    int excl = incl - v + wsum[wid];
    if (tid < SCAN_BLOCKS) g_blockoff[tid] = excl;
    if (tid == SCAN_BLOCKS - 1) g_rowptr[N_NODES] = excl + v;
}

__global__ void k_addoff() {
    int i = blockIdx.x * blockDim.x + threadIdx.x;
    if (i < N_NODES) {
        int v = g_rowptr[i] + g_blockoff[i >> 8];
        g_rowptr[i] = v;
        g_fill[i] = v;
    }
}

__global__ void k_scatter() {
    int e = blockIdx.x * blockDim.x + threadIdx.x;
    if (e < N_EDGES) {
        int s = g_esrc[e];
        int d = g_edst[e];
        int pos = atomicAdd(&g_fill[d], 1);
        if ((unsigned)pos < N_EDGES) {
            float w = g_dinv[s] * g_dinv[d];
            g_csr[pos] = make_int2(s, __float_as_int(w));
        }
    }
}

// ---------------- GEMM: g_h1[N,64] = X[N,KDIM] @ W[KDIM,64] ----------------
// 2-D register-tiled SGEMM with packed f32x2 accumulation.
// 512 threads/block, tile 128(M) x 64(N), BK=32; 4x4 micro-tile per thread.
// Per k: 1 LDS.128 (A) + 1 LDS.128 (B, reinterpreted as 2 aligned f32x2 pairs)
//        + 4 splat MOV (alu pipe) + 8 FFMA2 (fma pipe, half the scalar issue).
// A smem [k][m] XOR-swizzled: phys_f4(k,m4) = k*32 + (m4 ^ k)  (conflict-free
// for both transpose-staging stores and 16B compute loads).
template <int KDIM, int SRC>
__global__ void __launch_bounds__(512, 2)
k_gemm(const float* __restrict__ Xp, const float* __restrict__ W) {
    __shared__ float As[32 * 128];   // 16 KB, swizzled [k][m]
    __shared__ float Bs[32 * 64];    // 8 KB,  [k][n]
    const float* __restrict__ X = (SRC == 0) ? Xp : (const float*)g_h2;

    int tid = threadIdx.x;
    int base = blockIdx.x * 128;

    int lane = tid & 31;
    int w = tid >> 5;                    // warp id [0,16)
    int m_idx = (w & 3) * 8 + (lane & 7);
    int n_idx = (w >> 2) * 4 + (lane >> 3);

    // acc[i][p]: row i of micro-tile, p=0 -> cols (0,1), p=1 -> cols (2,3)
    unsigned long long acc[4][2];
#pragma unroll
    for (int i = 0; i < 4; i++) { acc[i][0] = 0ull; acc[i][1] = 0ull; }

    for (int k0 = 0; k0 < KDIM; k0 += 32) {
        __syncthreads();   // previous chunk fully consumed
        // stage A: X chunk [128 rows][32 k] = 1024 float4, 2 per thread,
        // transposed+swizzled scalar stores (conflict-free)
#pragma unroll
        for (int it = 0; it < 2; it++) {
            int idx = tid + 512 * it;      // 0..1023
            int r = idx >> 3;              // row 0..127
            int u4 = idx & 7;              // k-quad 0..7
            float4 v = make_float4(0.f, 0.f, 0.f, 0.f);
            int grow = base + r;
            if (grow < N_NODES)
                v = *(const float4*)&X[(size_t)grow * KDIM + k0 + u4 * 4];
            int m4 = r >> 2, c2 = r & 3;
            int kk = u4 * 4;
            As[((kk + 0) * 32 + (m4 ^ (kk + 0))) * 4 + c2] = v.x;
            As[((kk + 1) * 32 + (m4 ^ (kk + 1))) * 4 + c2] = v.y;
            As[((kk + 2) * 32 + (m4 ^ (kk + 2))) * 4 + c2] = v.z;
            As[((kk + 3) * 32 + (m4 ^ (kk + 3))) * 4 + c2] = v.w;
        }
        // stage B: W chunk [32][64] = 512 float4, 1 per thread
        {
            int k = tid >> 4;
            int n4 = tid & 15;
            *(float4*)&Bs[k * 64 + n4 * 4] =
                *(const float4*)&W[(size_t)(k0 + k) * 64 + n4 * 4];
        }
        __syncthreads();

#pragma unroll 8
        for (int k = 0; k < 32; k++) {
            float4 a = *(const float4*)&As[(k * 32 + (m_idx ^ k)) * 4];
            ulonglong2 b = *(const ulonglong2*)&Bs[k * 64 + n_idx * 4];
            unsigned long long ax = splat_f32x2(a.x);
            unsigned long long ay = splat_f32x2(a.y);
            unsigned long long az = splat_f32x2(a.z);
            unsigned long long aw = splat_f32x2(a.w);
            fma_f32x2(acc[0][0], ax, b.x); fma_f32x2(acc[0][1], ax, b.y);
            fma_f32x2(acc[1][0], ay, b.x); fma_f32x2(acc[1][1], ay, b.y);
            fma_f32x2(acc[2][0], az, b.x); fma_f32x2(acc[2][1], az, b.y);
            fma_f32x2(acc[3][0], aw, b.x); fma_f32x2(acc[3][1], aw, b.y);
        }
    }

#pragma unroll
    for (int i = 0; i < 4; i++) {
        int row = base + m_idx * 4 + i;
        if (row < N_NODES) {
            float2 lo = unpack_f32x2(acc[i][0]);
            float2 hi = unpack_f32x2(acc[i][1]);
            *(float4*)&g_h1[(size_t)row * 64 + n_idx * 4] =
                make_float4(lo.x, lo.y, hi.x, hi.y);
        }
    }
}

// ---------------- Aggregation + epilogue: warp per node ----------------
template <int MODE>
__global__ void k_agg(const float* __restrict__ bias, float* __restrict__ OUTp) {
    int gwarp = (blockIdx.x * blockDim.x + threadIdx.x) >> 5;
    int lane = threadIdx.x & 31;
    if (gwarp >= N_NODES) return;
    int i = gwarp;

    float di = g_dinv[i];
    int beg = g_rowptr[i];
    int end = g_rowptr[i + 1];

    const float2* __restrict__ H2 = (const float2*)g_h1;
    float2 hv = H2[(size_t)i * 32 + lane];
    float wself = di * di;
    float a0 = wself * hv.x;
    float a1 = wself * hv.y;

    int j = beg;
    for (; j + 4 <= end; j += 4) {
        int2 e0 = g_csr[j + 0];
        int2 e1 = g_csr[j + 1];
        int2 e2 = g_csr[j + 2];
        int2 e3 = g_csr[j + 3];
        float2 h0 = H2[(size_t)e0.x * 32 + lane];
        float2 h1v = H2[(size_t)e1.x * 32 + lane];
        float2 h2v = H2[(size_t)e2.x * 32 + lane];
        float2 h3 = H2[(size_t)e3.x * 32 + lane];
        a0 += __int_as_float(e0.y) * h0.x;  a1 += __int_as_float(e0.y) * h0.y;
        a0 += __int_as_float(e1.y) * h1v.x; a1 += __int_as_float(e1.y) * h1v.y;
        a0 += __int_as_float(e2.y) * h2v.x; a1 += __int_as_float(e2.y) * h2v.y;
        a0 += __int_as_float(e3.y) * h3.x;  a1 += __int_as_float(e3.y) * h3.y;
    }
    for (; j < end; j++) {
        int2 sw = g_csr[j];
        float w = __int_as_float(sw.y);
        float2 hs = H2[(size_t)sw.x * 32 + lane];
        a0 += w * hs.x;
        a1 += w * hs.y;
    }

    float2 b = ((const float2*)bias)[lane];
    a0 += b.x;
    a1 += b.y;

    if (MODE == 1) {
        a0 = fmaxf(a0, 0.f);
        a1 = fmaxf(a1, 0.f);
        float ss = a0 * a0 + a1 * a1;
#pragma unroll
        for (int o = 16; o; o >>= 1) ss += __shfl_xor_sync(0xffffffffu, ss, o);
        float inv = 1.f / fmaxf(sqrtf(ss), 1e-12f);
        a0 *= inv;
        a1 *= inv;
        ((float2*)g_h2)[(size_t)i * 32 + lane] = make_float2(a0, a1);
    } else {
        ((float2*)OUTp)[(size_t)i * 32 + lane] = make_float2(a0, a1);
    }
}

// ---------------- launch ----------------
extern "C" void kernel_launch(void* const* d_in, const int* in_sizes, int n_in,
                              void* d_out, int out_size) {
    const float* x = (const float*)d_in[0];
    const int* ei = (const int*)d_in[1];     // int32 edge_index [2, E]
    const float* W1 = (const float*)d_in[2];
    const float* b1 = (const float*)d_in[3];
    const float* W2 = (const float*)d_in[4];
    const float* b2 = (const float*)d_in[5];
    const float* W3 = (const float*)d_in[6];
    const float* b3 = (const float*)d_in[7];
    float* out = (float*)d_out;

    const int T = 256;
    int gemm_grid = (N_NODES + 127) / 128;
    int agg_grid = (N_NODES * 32 + T - 1) / T;

    // preprocessing with gemm1 at launch index 3 (ncu capture target)
    k_init_deg<<<SCAN_BLOCKS, T>>>();                       // 0
    k_hist<<<(N_EDGES + T - 1) / T, T>>>(ei);               // 1
    k_blockscan<<<SCAN_BLOCKS, T>>>();                      // 2
    k_gemm<256, 0><<<gemm_grid, 512>>>(x, W1);              // 3  <- profiled
    k_scanmid<<<1, 512>>>();                                // 4
    k_addoff<<<SCAN_BLOCKS, T>>>();                         // 5
    k_scatter<<<(N_EDGES + T - 1) / T, T>>>();              // 6

    // layer 1 aggregation
    k_agg<1><<<agg_grid, T>>>(b1, nullptr);                 // 7
    // layer 2
    k_gemm<64, 1><<<gemm_grid, 512>>>(nullptr, W2);         // 8
    k_agg<1><<<agg_grid, T>>>(b2, nullptr);                 // 9
    // layer 3
    k_gemm<64, 1><<<gemm_grid, 512>>>(nullptr, W3);         // 10
    k_agg<0><<<agg_grid, T>>>(b3, out);                     // 11
}

// round 9
// speedup vs baseline: 1.3801x; 1.0995x over previous
#include <cuda_runtime.h>
#include <cuda_bf16.h>
#include <cuda_fp16.h>
#include <math.h>

#define N_NODES 100000
#define N_EDGES 1600000
#define HID 64
#define SCAN_BLOCKS ((N_NODES + 255) / 256)   // 391

// ---------------- scratch (static device memory; no allocations) ----------------
__device__ int     g_deg[N_NODES];
__device__ float   g_dinv[N_NODES];
__device__ int     g_rowptr[N_NODES + 1];
__device__ int     g_fill[N_NODES];
__device__ int     g_esrc[N_EDGES];
__device__ int     g_edst[N_EDGES];
__device__ int2    g_csr[N_EDGES];            // .x = src, .y = bits of norm weight
__device__ __half2 g_h1h[(size_t)N_NODES * 32];  // GEMM output, fp16 (gather operand)
__device__ float   g_h2[(size_t)N_NODES * HID];  // agg output, fp32 (GEMM input)
__device__ int     g_blocksum[SCAN_BLOCKS];
__device__ int     g_blockoff[SCAN_BLOCKS];

// ---------------- packed f32x2 helpers ----------------
__device__ __forceinline__ unsigned long long splat_f32x2(float x) {
    unsigned long long r;
    asm("mov.b64 %0, {%1, %1};" : "=l"(r) : "f"(x));
    return r;
}
__device__ __forceinline__ void fma_f32x2(unsigned long long& d,
                                          unsigned long long a,
                                          unsigned long long b) {
    asm("fma.rn.f32x2 %0, %1, %2, %0;" : "+l"(d) : "l"(a), "l"(b));
}
__device__ __forceinline__ float2 unpack_f32x2(unsigned long long v) {
    float2 f;
    asm("mov.b64 {%0, %1}, %2;" : "=f"(f.x), "=f"(f.y) : "l"(v));
    return f;
}

// ---------------- preprocessing ----------------
__global__ void k_init_deg() {
    int i = blockIdx.x * blockDim.x + threadIdx.x;
    if (i < N_NODES) g_deg[i] = 1;   // self-loop
}

__global__ void k_hist(const int* __restrict__ ei) {
    int e = blockIdx.x * blockDim.x + threadIdx.x;
    if (e < N_EDGES) {
        int s = ei[e];
        int d = ei[N_EDGES + e];
        if ((unsigned)s >= N_NODES) s = 0;
        if ((unsigned)d >= N_NODES) d = 0;
        g_esrc[e] = s;
        g_edst[e] = d;
        atomicAdd(&g_deg[d], 1);
    }
}

// block-level exclusive scan of (deg-1); also computes dinv. 391 blocks x 256.
__global__ void k_blockscan() {
    __shared__ int wsum[8];
    int tid = threadIdx.x;
    int lane = tid & 31;
    int wid = tid >> 5;
    int i = blockIdx.x * 256 + tid;

    int e = 0;
    if (i < N_NODES) {
        int dg = g_deg[i];
        g_dinv[i] = rsqrtf((float)dg);
        e = dg - 1;
    }
    int incl = e;
#pragma unroll
    for (int o = 1; o < 32; o <<= 1) {
        int v = __shfl_up_sync(0xffffffffu, incl, o);
        if (lane >= o) incl += v;
    }
    if (lane == 31) wsum[wid] = incl;
    __syncthreads();
    if (wid == 0) {
        int v = (lane < 8) ? wsum[lane] : 0;
        int s = v;
#pragma unroll
        for (int o = 1; o < 8; o <<= 1) {
            int u = __shfl_up_sync(0xffffffffu, s, o);
            if (lane >= o) s += u;
        }
        if (lane < 8) wsum[lane] = s - v;
    }
    __syncthreads();
    int excl = incl - e + wsum[wid];
    if (i < N_NODES) g_rowptr[i] = excl;       // partial (block-local)
    if (tid == 255) g_blocksum[blockIdx.x] = excl + e;
}

// 1 block, 512 threads: exclusive scan of 391 block sums.
__global__ void k_scanmid() {
    __shared__ int wsum[16];
    int tid = threadIdx.x;
    int lane = tid & 31;
    int wid = tid >> 5;
    int v = (tid < SCAN_BLOCKS) ? g_blocksum[tid] : 0;
    int incl = v;
#pragma unroll
    for (int o = 1; o < 32; o <<= 1) {
        int u = __shfl_up_sync(0xffffffffu, incl, o);
        if (lane >= o) incl += u;
    }
    if (lane == 31) wsum[wid] = incl;
    __syncthreads();
    if (wid == 0) {
        int w = (lane < 16) ? wsum[lane] : 0;
        int s = w;
#pragma unroll
        for (int o = 1; o < 16; o <<= 1) {
            int u = __shfl_up_sync(0xffffffffu, s, o);
            if (lane >= o) s += u;
        }
        if (lane < 16) wsum[lane] = s - w;
    }
    __syncthreads();
    int excl = incl - v + wsum[wid];
    if (tid < SCAN_BLOCKS) g_blockoff[tid] = excl;
    if (tid == SCAN_BLOCKS - 1) g_rowptr[N_NODES] = excl + v;
}

__global__ void k_addoff() {
    int i = blockIdx.x * blockDim.x + threadIdx.x;
    if (i < N_NODES) {
        int v = g_rowptr[i] + g_blockoff[i >> 8];
        g_rowptr[i] = v;
        g_fill[i] = v;
    }
}

__global__ void k_scatter() {
    int e = blockIdx.x * blockDim.x + threadIdx.x;
    if (e < N_EDGES) {
        int s = g_esrc[e];
        int d = g_edst[e];
        int pos = atomicAdd(&g_fill[d], 1);
        if ((unsigned)pos < N_EDGES) {
            float w = g_dinv[s] * g_dinv[d];
            g_csr[pos] = make_int2(s, __float_as_int(w));
        }
    }
}

// ---------------- GEMM: g_h1h[N,64](fp16) = X[N,KDIM](fp32) @ W[KDIM,64] ----------------
// 128 threads/block, tile 128(M) x 64(N), BK=32; 8x8 micro-tile per thread.
// Per k: 2 LDS.128 (A granules (2m)^k,(2m+1)^k) + 2 LDS.128 (B) feed
// 64 FMA (32 FFMA2) -> 1 B/FMA of LDS traffic (half of the 4x4 design).
// As layout identical to previous (verified) kernel: [k][m] XOR-swizzled,
// phys_f4(k,m4) = k*32 + (m4 ^ k). Bs [k][n] row-major.
template <int KDIM, int SRC>
__global__ void __launch_bounds__(128, 4)
k_gemm(const float* __restrict__ Xp, const float* __restrict__ W) {
    __shared__ float As[32 * 128];   // 16 KB, swizzled [k][m]
    __shared__ float Bs[32 * 64];    // 8 KB,  [k][n]
    const float* __restrict__ X = (SRC == 0) ? Xp : (const float*)g_h2;

    int tid = threadIdx.x;
    int base = blockIdx.x * 128;

    int m_idx = tid & 15;            // 16 m-groups of 8 rows
    int n_idx = tid >> 4;            // 8 n-groups of 8 cols

    // acc[i][p]: micro-row i (0..7), p indexes col pair (2p, 2p+1)
    unsigned long long acc[8][4];
#pragma unroll
    for (int i = 0; i < 8; i++)
#pragma unroll
        for (int p = 0; p < 4; p++) acc[i][p] = 0ull;

    for (int k0 = 0; k0 < KDIM; k0 += 32) {
        __syncthreads();   // previous chunk fully consumed
        // stage A: X chunk [128 rows][32 k] = 1024 float4, 8 per thread,
        // transposed+swizzled scalar stores (same pattern as prior rounds)
#pragma unroll
        for (int it = 0; it < 8; it++) {
            int idx = tid + 128 * it;      // 0..1023
            int r = idx >> 3;              // row 0..127
            int u4 = idx & 7;              // k-quad 0..7
            float4 v = make_float4(0.f, 0.f, 0.f, 0.f);
            int grow = base + r;
            if (grow < N_NODES)
                v = *(const float4*)&X[(size_t)grow * KDIM + k0 + u4 * 4];
            int m4 = r >> 2, c2 = r & 3;
            int kk = u4 * 4;
            As[((kk + 0) * 32 + (m4 ^ (kk + 0))) * 4 + c2] = v.x;
            As[((kk + 1) * 32 + (m4 ^ (kk + 1))) * 4 + c2] = v.y;
            As[((kk + 2) * 32 + (m4 ^ (kk + 2))) * 4 + c2] = v.z;
            As[((kk + 3) * 32 + (m4 ^ (kk + 3))) * 4 + c2] = v.w;
        }
        // stage B: W chunk [32][64] = 512 float4, 4 per thread
#pragma unroll
        for (int it = 0; it < 4; it++) {
            int idx = tid + 128 * it;
            int k = idx >> 4;
            int n4 = idx & 15;
            *(float4*)&Bs[k * 64 + n4 * 4] =
                *(const float4*)&W[(size_t)(k0 + k) * 64 + n4 * 4];
        }
        __syncthreads();

#pragma unroll 4
        for (int k = 0; k < 32; k++) {
            float4 a0 = *(const float4*)&As[(k * 32 + ((2 * m_idx + 0) ^ k)) * 4];
            float4 a1 = *(const float4*)&As[(k * 32 + ((2 * m_idx + 1) ^ k)) * 4];
            ulonglong2 bl = *(const ulonglong2*)&Bs[k * 64 + n_idx * 8];
            ulonglong2 bh = *(const ulonglong2*)&Bs[k * 64 + n_idx * 8 + 4];
            unsigned long long s0 = splat_f32x2(a0.x);
            unsigned long long s1 = splat_f32x2(a0.y);
            unsigned long long s2 = splat_f32x2(a0.z);
            unsigned long long s3 = splat_f32x2(a0.w);
            unsigned long long s4 = splat_f32x2(a1.x);
            unsigned long long s5 = splat_f32x2(a1.y);
            unsigned long long s6 = splat_f32x2(a1.z);
            unsigned long long s7 = splat_f32x2(a1.w);
            fma_f32x2(acc[0][0], s0, bl.x); fma_f32x2(acc[0][1], s0, bl.y);
            fma_f32x2(acc[0][2], s0, bh.x); fma_f32x2(acc[0][3], s0, bh.y);
            fma_f32x2(acc[1][0], s1, bl.x); fma_f32x2(acc[1][1], s1, bl.y);
            fma_f32x2(acc[1][2], s1, bh.x); fma_f32x2(acc[1][3], s1, bh.y);
            fma_f32x2(acc[2][0], s2, bl.x); fma_f32x2(acc[2][1], s2, bl.y);
            fma_f32x2(acc[2][2], s2, bh.x); fma_f32x2(acc[2][3], s2, bh.y);
            fma_f32x2(acc[3][0], s3, bl.x); fma_f32x2(acc[3][1], s3, bl.y);
            fma_f32x2(acc[3][2], s3, bh.x); fma_f32x2(acc[3][3], s3, bh.y);
            fma_f32x2(acc[4][0], s4, bl.x); fma_f32x2(acc[4][1], s4, bl.y);
            fma_f32x2(acc[4][2], s4, bh.x); fma_f32x2(acc[4][3], s4, bh.y);
            fma_f32x2(acc[5][0], s5, bl.x); fma_f32x2(acc[5][1], s5, bl.y);
            fma_f32x2(acc[5][2], s5, bh.x); fma_f32x2(acc[5][3], s5, bh.y);
            fma_f32x2(acc[6][0], s6, bl.x); fma_f32x2(acc[6][1], s6, bl.y);
            fma_f32x2(acc[6][2], s6, bh.x); fma_f32x2(acc[6][3], s6, bh.y);
            fma_f32x2(acc[7][0], s7, bl.x); fma_f32x2(acc[7][1], s7, bl.y);
            fma_f32x2(acc[7][2], s7, bh.x); fma_f32x2(acc[7][3], s7, bh.y);
        }
    }

    // epilogue: convert 8x8 fp32 micro-tile to fp16, one ST.128 per row
#pragma unroll
    for (int i = 0; i < 8; i++) {
        int row = base + m_idx * 8 + i;
        if (row < N_NODES) {
            __half2 h[4];
#pragma unroll
            for (int p = 0; p < 4; p++)
                h[p] = __float22half2_rn(unpack_f32x2(acc[i][p]));
            *(uint4*)&g_h1h[(size_t)row * 32 + n_idx * 4] = *(uint4*)h;
        }
    }
}

// ---------------- Aggregation + epilogue: warp per node ----------------
// OUT[i] = sum_{e: dst=i} w_e * h1h[src_e] + dinv[i]^2 * h1h[i] + bias
// h1h is fp16 (half gather bytes); accumulation in fp32.
template <int MODE>
__global__ void k_agg(const float* __restrict__ bias, float* __restrict__ OUTp) {
    int gwarp = (blockIdx.x * blockDim.x + threadIdx.x) >> 5;
    int lane = threadIdx.x & 31;
    if (gwarp >= N_NODES) return;
    int i = gwarp;

    float di = g_dinv[i];
    int beg = g_rowptr[i];
    int end = g_rowptr[i + 1];

    const __half2* __restrict__ H = g_h1h;
    float2 hv = __half22float2(H[(size_t)i * 32 + lane]);
    float wself = di * di;
    float a0 = wself * hv.x;
    float a1 = wself * hv.y;

    int j = beg;
    for (; j + 4 <= end; j += 4) {
        int2 e0 = g_csr[j + 0];
        int2 e1 = g_csr[j + 1];
        int2 e2 = g_csr[j + 2];
        int2 e3 = g_csr[j + 3];
        float2 h0 = __half22float2(H[(size_t)e0.x * 32 + lane]);
        float2 h1v = __half22float2(H[(size_t)e1.x * 32 + lane]);
        float2 h2v = __half22float2(H[(size_t)e2.x * 32 + lane]);
        float2 h3 = __half22float2(H[(size_t)e3.x * 32 + lane]);
        a0 += __int_as_float(e0.y) * h0.x;  a1 += __int_as_float(e0.y) * h0.y;
        a0 += __int_as_float(e1.y) * h1v.x; a1 += __int_as_float(e1.y) * h1v.y;
        a0 += __int_as_float(e2.y) * h2v.x; a1 += __int_as_float(e2.y) * h2v.y;
        a0 += __int_as_float(e3.y) * h3.x;  a1 += __int_as_float(e3.y) * h3.y;
    }
    for (; j < end; j++) {
        int2 sw = g_csr[j];
        float w = __int_as_float(sw.y);
        float2 hs = __half22float2(H[(size_t)sw.x * 32 + lane]);
        a0 += w * hs.x;
        a1 += w * hs.y;
    }

    float2 b = ((const float2*)bias)[lane];
    a0 += b.x;
    a1 += b.y;

    if (MODE == 1) {
        a0 = fmaxf(a0, 0.f);
        a1 = fmaxf(a1, 0.f);
        float ss = a0 * a0 + a1 * a1;
#pragma unroll
        for (int o = 16; o; o >>= 1) ss += __shfl_xor_sync(0xffffffffu, ss, o);
        float inv = 1.f / fmaxf(sqrtf(ss), 1e-12f);
        a0 *= inv;
        a1 *= inv;
        ((float2*)g_h2)[(size_t)i * 32 + lane] = make_float2(a0, a1);
    } else {
        ((float2*)OUTp)[(size_t)i * 32 + lane] = make_float2(a0, a1);
    }
}

// ---------------- launch ----------------
extern "C" void kernel_launch(void* const* d_in, const int* in_sizes, int n_in,
                              void* d_out, int out_size) {
    const float* x = (const float*)d_in[0];
    const int* ei = (const int*)d_in[1];     // int32 edge_index [2, E]
    const float* W1 = (const float*)d_in[2];
    const float* b1 = (const float*)d_in[3];
    const float* W2 = (const float*)d_in[4];
    const float* b2 = (const float*)d_in[5];
    const float* W3 = (const float*)d_in[6];
    const float* b3 = (const float*)d_in[7];
    float* out = (float*)d_out;

    const int T = 256;
    int gemm_grid = (N_NODES + 127) / 128;
    int agg_grid = (N_NODES * 32 + T - 1) / T;

    // preprocessing with gemm1 at launch index 3 (ncu capture target)
    k_init_deg<<<SCAN_BLOCKS, T>>>();                       // 0
    k_hist<<<(N_EDGES + T - 1) / T, T>>>(ei);               // 1
    k_blockscan<<<SCAN_BLOCKS, T>>>();                      // 2
    k_gemm<256, 0><<<gemm_grid, 128>>>(x, W1);              // 3  <- profiled
    k_scanmid<<<1, 512>>>();                                // 4
    k_addoff<<<SCAN_BLOCKS, T>>>();                         // 5
    k_scatter<<<(N_EDGES + T - 1) / T, T>>>();              // 6

    // layer 1 aggregation
    k_agg<1><<<agg_grid, T>>>(b1, nullptr);                 // 7
    // layer 2
    k_gemm<64, 1><<<gemm_grid, 128>>>(nullptr, W2);         // 8
    k_agg<1><<<agg_grid, T>>>(b2, nullptr);                 // 9
    // layer 3
    k_gemm<64, 1><<<gemm_grid, 128>>>(nullptr, W3);         // 10
    k_agg<0><<<agg_grid, T>>>(b3, out);                     // 11
}

// round 11
// speedup vs baseline: 1.9290x; 1.3977x over previous
#include <cuda_runtime.h>
#include <cuda_bf16.h>
#include <cuda_fp16.h>
#include <mma.h>
#include <math.h>
#include <stdint.h>

using namespace nvcuda;

#define N_NODES 100000
#define N_EDGES 1600000
#define HID 64
#define SCAN_BLOCKS ((N_NODES + 255) / 256)   // 391

// ---------------- scratch (static device memory; no allocations) ----------------
__device__ int     g_deg[N_NODES];
__device__ float   g_dinv[N_NODES];
__device__ int     g_rowptr[N_NODES + 1];
__device__ int     g_fill[N_NODES];
__device__ int     g_esrc[N_EDGES];
__device__ int     g_edst[N_EDGES];
__device__ int2    g_csr[N_EDGES];               // .x = src, .y = bits of norm weight
__device__ __half2 g_h1h[(size_t)N_NODES * 32];  // GEMM output (gather operand), fp16
__device__ __half2 g_h2h[(size_t)N_NODES * 32];  // agg output (GEMM input), fp16
__device__ int     g_blocksum[SCAN_BLOCKS];
__device__ int     g_blockoff[SCAN_BLOCKS];

// ---------------- preprocessing ----------------
__global__ void k_init_deg() {
    int i = blockIdx.x * blockDim.x + threadIdx.x;
    if (i < N_NODES) g_deg[i] = 1;   // self-loop
}

__global__ void k_hist(const int* __restrict__ ei) {
    int e = blockIdx.x * blockDim.x + threadIdx.x;
    if (e < N_EDGES) {
        int s = ei[e];
        int d = ei[N_EDGES + e];
        if ((unsigned)s >= N_NODES) s = 0;
        if ((unsigned)d >= N_NODES) d = 0;
        g_esrc[e] = s;
        g_edst[e] = d;
        atomicAdd(&g_deg[d], 1);
    }
}

__global__ void k_blockscan() {
    __shared__ int wsum[8];
    int tid = threadIdx.x;
    int lane = tid & 31;
    int wid = tid >> 5;
    int i = blockIdx.x * 256 + tid;

    int e = 0;
    if (i < N_NODES) {
        int dg = g_deg[i];
        g_dinv[i] = rsqrtf((float)dg);
        e = dg - 1;
    }
    int incl = e;
#pragma unroll
    for (int o = 1; o < 32; o <<= 1) {
        int v = __shfl_up_sync(0xffffffffu, incl, o);
        if (lane >= o) incl += v;
    }
    if (lane == 31) wsum[wid] = incl;
    __syncthreads();
    if (wid == 0) {
        int v = (lane < 8) ? wsum[lane] : 0;
        int s = v;
#pragma unroll
        for (int o = 1; o < 8; o <<= 1) {
            int u = __shfl_up_sync(0xffffffffu, s, o);
            if (lane >= o) s += u;
        }
        if (lane < 8) wsum[lane] = s - v;
    }
    __syncthreads();
    int excl = incl - e + wsum[wid];
    if (i < N_NODES) g_rowptr[i] = excl;
    if (tid == 255) g_blocksum[blockIdx.x] = excl + e;
}

__global__ void k_scanmid() {
    __shared__ int wsum[16];
    int tid = threadIdx.x;
    int lane = tid & 31;
    int wid = tid >> 5;
    int v = (tid < SCAN_BLOCKS) ? g_blocksum[tid] : 0;
    int incl = v;
#pragma unroll
    for (int o = 1; o < 32; o <<= 1) {
        int u = __shfl_up_sync(0xffffffffu, incl, o);
        if (lane >= o) incl += u;
    }
    if (lane == 31) wsum[wid] = incl;
    __syncthreads();
    if (wid == 0) {
        int w = (lane < 16) ? wsum[lane] : 0;
        int s = w;
#pragma unroll
        for (int o = 1; o < 16; o <<= 1) {
            int u = __shfl_up_sync(0xffffffffu, s, o);
            if (lane >= o) s += u;
        }
        if (lane < 16) wsum[lane] = s - w;
    }
    __syncthreads();
    int excl = incl - v + wsum[wid];
    if (tid < SCAN_BLOCKS) g_blockoff[tid] = excl;
    if (tid == SCAN_BLOCKS - 1) g_rowptr[N_NODES] = excl + v;
}

__global__ void k_addoff() {
    int i = blockIdx.x * blockDim.x + threadIdx.x;
    if (i < N_NODES) {
        int v = g_rowptr[i] + g_blockoff[i >> 8];
        g_rowptr[i] = v;
        g_fill[i] = v;
    }
}

__global__ void k_scatter() {
    int e = blockIdx.x * blockDim.x + threadIdx.x;
    if (e < N_EDGES) {
        int s = g_esrc[e];
        int d = g_edst[e];
        int pos = atomicAdd(&g_fill[d], 1);
        if ((unsigned)pos < N_EDGES) {
            float w = g_dinv[s] * g_dinv[d];
            g_csr[pos] = make_int2(s, __float_as_int(w));
        }
    }
}

// ---------------- HMMA GEMM: g_h1h[N,64](fp16) = X[N,KDIM] @ W[KDIM,64] ------
// 128 threads (4 warps), tile M=128 x N=64, K chunked by 64.
// Warp w owns rows [w*32, w*32+32) as 2(m) x 4(n) wmma 16x16x16 fragments,
// fp16 inputs, fp32 accumulators (HMMA; no sm_103a-only features).
// Smem: As[128][72] fp16 (18.0KB) + Bs[64][72] fp16 (9.0KB), union'd with
// Cs[128][68] fp32 (34.8KB) for the epilogue.
// SRC=0: X = fp32 param (layer 1).  SRC=1: X = g_h2h fp16 (layers 2,3).
template <int KDIM, int SRC>
__global__ void __launch_bounds__(128)
k_gemm_mma(const float* __restrict__ Xp, const float* __restrict__ Wp) {
    constexpr int LDA = 72;   // halves per As/Bs row (144B, 16B-aligned)
    constexpr int LDC = 68;   // floats per Cs row (272B)
    __shared__ __align__(16) char sbuf[128 * LDC * 4];   // 34816 B
    __half* As = (__half*)sbuf;                          // 128*72*2 = 18432
    __half* Bs = (__half*)(sbuf + 128 * LDA * 2);        // 64*72*2  =  9216
    float*  Cs = (float*)sbuf;

    int tid = threadIdx.x;
    int wid = tid >> 5;
    int base = blockIdx.x * 128;
    int m0 = wid * 32;

    wmma::fragment<wmma::accumulator, 16, 16, 16, float> acc[2][4];
#pragma unroll
    for (int i = 0; i < 2; i++)
#pragma unroll
        for (int j = 0; j < 4; j++) wmma::fill_fragment(acc[i][j], 0.f);

    const int NCHUNK = KDIM / 64;
    for (int c = 0; c < NCHUNK; c++) {
        __syncthreads();   // previous chunk fully consumed
        // ---- stage A chunk: rows [base,base+128), k in [c*64, c*64+64) ----
        if (SRC == 0) {
#pragma unroll
            for (int it = 0; it < 8; it++) {
                int idx = tid + 128 * it;      // 0..1023
                int r = idx >> 3;              // row 0..127
                int k8 = idx & 7;              // 8-half segment
                float4 v0 = make_float4(0.f, 0.f, 0.f, 0.f);
                float4 v1 = make_float4(0.f, 0.f, 0.f, 0.f);
                int grow = base + r;
                if (grow < N_NODES) {
                    const float* xr = &Xp[(size_t)grow * KDIM + c * 64 + k8 * 8];
                    v0 = *(const float4*)xr;
                    v1 = *(const float4*)(xr + 4);
                }
                __half2 h[4];
                h[0] = __floats2half2_rn(v0.x, v0.y);
                h[1] = __floats2half2_rn(v0.z, v0.w);
                h[2] = __floats2half2_rn(v1.x, v1.y);
                h[3] = __floats2half2_rn(v1.z, v1.w);
                *(uint4*)&As[r * LDA + k8 * 8] = *(uint4*)h;
            }
        } else {
            const uint4* X = (const uint4*)g_h2h;   // 8 uint4 per 64-half row
#pragma unroll
            for (int it = 0; it < 8; it++) {
                int idx = tid + 128 * it;
                int r = idx >> 3;
                int k8 = idx & 7;
                uint4 v = make_uint4(0u, 0u, 0u, 0u);
                int grow = base + r;
                if (grow < N_NODES) v = X[(size_t)grow * 8 + k8];
                *(uint4*)&As[r * LDA + k8 * 8] = v;
            }
        }
        // ---- stage B chunk: Bs[k][n] = W[c*64+k][n], row-major ----
#pragma unroll
        for (int it = 0; it < 4; it++) {
            int idx = tid + 128 * it;          // 0..511
            int k = idx >> 3;                  // 0..63
            int n8 = idx & 7;
            const float* wr = &Wp[(size_t)(c * 64 + k) * 64 + n8 * 8];
            float4 v0 = *(const float4*)wr;
            float4 v1 = *(const float4*)(wr + 4);
            __half2 h[4];
            h[0] = __floats2half2_rn(v0.x, v0.y);
            h[1] = __floats2half2_rn(v0.z, v0.w);
            h[2] = __floats2half2_rn(v1.x, v1.y);
            h[3] = __floats2half2_rn(v1.z, v1.w);
            *(uint4*)&Bs[k * LDA + n8 * 8] = *(uint4*)h;
        }
        __syncthreads();

        // ---- 4 k-steps of 16 ----
#pragma unroll
        for (int kk = 0; kk < 4; kk++) {
            wmma::fragment<wmma::matrix_a, 16, 16, 16, __half, wmma::row_major> a[2];
            wmma::fragment<wmma::matrix_b, 16, 16, 16, __half, wmma::row_major> b[4];
#pragma unroll
            for (int i = 0; i < 2; i++)
                wmma::load_matrix_sync(a[i], &As[(m0 + i * 16) * LDA + kk * 16], LDA);
#pragma unroll
            for (int j = 0; j < 4; j++)
                wmma::load_matrix_sync(b[j], &Bs[kk * 16 * LDA + j * 16], LDA);
#pragma unroll
            for (int i = 0; i < 2; i++)
#pragma unroll
                for (int j = 0; j < 4; j++)
                    wmma::mma_sync(acc[i][j], a[i], b[j], acc[i][j]);
        }
    }

    // ---- epilogue: fragments -> Cs (fp32) -> g_h1h (fp16) ----
    __syncthreads();   // all warps done reading As/Bs (Cs aliases them)
#pragma unroll
    for (int i = 0; i < 2; i++)
#pragma unroll
        for (int j = 0; j < 4; j++)
            wmma::store_matrix_sync(&Cs[(m0 + i * 16) * LDC + j * 16], acc[i][j],
                                    LDC, wmma::mem_row_major);
    __syncthreads();

    int row = base + tid;
    if (row < N_NODES) {
        const float* cr = &Cs[tid * LDC];
        __half2 h[32];
#pragma unroll
        for (int p = 0; p < 32; p++) {
            float2 f = *(const float2*)&cr[2 * p];
            h[p] = __floats2half2_rn(f.x, f.y);
        }
        uint4* o = (uint4*)&g_h1h[(size_t)row * 32];
#pragma unroll
        for (int q = 0; q < 8; q++) o[q] = ((uint4*)h)[q];
    }
}

// ---------------- Aggregation + epilogue: warp per node ----------------
// OUT[i] = sum_{e: dst=i} w_e * h1h[src_e] + dinv[i]^2 * h1h[i] + bias
// MODE=1: relu + L2-normalize -> g_h2h (fp16).  MODE=0: plain -> OUTp (fp32).
template <int MODE>
__global__ void k_agg(const float* __restrict__ bias, float* __restrict__ OUTp) {
    int gwarp = (blockIdx.x * blockDim.x + threadIdx.x) >> 5;
    int lane = threadIdx.x & 31;
    if (gwarp >= N_NODES) return;
    int i = gwarp;

    float di = g_dinv[i];
    int beg = g_rowptr[i];
    int end = g_rowptr[i + 1];

    const __half2* __restrict__ H = g_h1h;
    float2 hv = __half22float2(H[(size_t)i * 32 + lane]);
    float wself = di * di;
    float a0 = wself * hv.x;
    float a1 = wself * hv.y;

    int j = beg;
    for (; j + 4 <= end; j += 4) {
        int2 e0 = g_csr[j + 0];
        int2 e1 = g_csr[j + 1];
        int2 e2 = g_csr[j + 2];
        int2 e3 = g_csr[j + 3];
        float2 h0 = __half22float2(H[(size_t)e0.x * 32 + lane]);
        float2 h1v = __half22float2(H[(size_t)e1.x * 32 + lane]);
        float2 h2v = __half22float2(H[(size_t)e2.x * 32 + lane]);
        float2 h3 = __half22float2(H[(size_t)e3.x * 32 + lane]);
        a0 += __int_as_float(e0.y) * h0.x;  a1 += __int_as_float(e0.y) * h0.y;
        a0 += __int_as_float(e1.y) * h1v.x; a1 += __int_as_float(e1.y) * h1v.y;
        a0 += __int_as_float(e2.y) * h2v.x; a1 += __int_as_float(e2.y) * h2v.y;
        a0 += __int_as_float(e3.y) * h3.x;  a1 += __int_as_float(e3.y) * h3.y;
    }
    for (; j < end; j++) {
        int2 sw = g_csr[j];
        float w = __int_as_float(sw.y);
        float2 hs = __half22float2(H[(size_t)sw.x * 32 + lane]);
        a0 += w * hs.x;
        a1 += w * hs.y;
    }

    float2 b = ((const float2*)bias)[lane];
    a0 += b.x;
    a1 += b.y;

    if (MODE == 1) {
        a0 = fmaxf(a0, 0.f);
        a1 = fmaxf(a1, 0.f);
        float ss = a0 * a0 + a1 * a1;
#pragma unroll
        for (int o = 16; o; o >>= 1) ss += __shfl_xor_sync(0xffffffffu, ss, o);
        float inv = 1.f / fmaxf(sqrtf(ss), 1e-12f);
        a0 *= inv;
        a1 *= inv;
        g_h2h[(size_t)i * 32 + lane] = __floats2half2_rn(a0, a1);
    } else {
        ((float2*)OUTp)[(size_t)i * 32 + lane] = make_float2(a0, a1);
    }
}

// ---------------- launch ----------------
extern "C" void kernel_launch(void* const* d_in, const int* in_sizes, int n_in,
                              void* d_out, int out_size) {
    const float* x = (const float*)d_in[0];
    const int* ei = (const int*)d_in[1];     // int32 edge_index [2, E]
    const float* W1 = (const float*)d_in[2];
    const float* b1 = (const float*)d_in[3];
    const float* W2 = (const float*)d_in[4];
    const float* b2 = (const float*)d_in[5];
    const float* W3 = (const float*)d_in[6];
    const float* b3 = (const float*)d_in[7];
    float* out = (float*)d_out;

    const int T = 256;
    int gemm_grid = (N_NODES + 127) / 128;
    int agg_grid = (N_NODES * 32 + T - 1) / T;

    // preprocessing with gemm1 at launch index 3 (ncu capture target)
    k_init_deg<<<SCAN_BLOCKS, T>>>();                       // 0
    k_hist<<<(N_EDGES + T - 1) / T, T>>>(ei);               // 1
    k_blockscan<<<SCAN_BLOCKS, T>>>();                      // 2
    k_gemm_mma<256, 0><<<gemm_grid, 128>>>(x, W1);          // 3  <- profiled
    k_scanmid<<<1, 512>>>();                                // 4
    k_addoff<<<SCAN_BLOCKS, T>>>();                         // 5
    k_scatter<<<(N_EDGES + T - 1) / T, T>>>();              // 6

    // layer 1 aggregation
    k_agg<1><<<agg_grid, T>>>(b1, nullptr);                 // 7
    // layer 2
    k_gemm_mma<64, 1><<<gemm_grid, 128>>>(nullptr, W2);     // 8
    k_agg<1><<<agg_grid, T>>>(b2, nullptr);                 // 9
    // layer 3
    k_gemm_mma<64, 1><<<gemm_grid, 128>>>(nullptr, W3);     // 10
    k_agg<0><<<agg_grid, T>>>(b3, out);                     // 11
}

// round 12
// speedup vs baseline: 1.9433x; 1.0074x over previous
#include <cuda_runtime.h>
#include <cuda_bf16.h>
#include <cuda_fp16.h>
#include <mma.h>
#include <math.h>
#include <stdint.h>

using namespace nvcuda;

#define N_NODES 100000
#define N_EDGES 1600000
#define HID 64
#define SCAN_BLOCKS ((N_NODES + 255) / 256)   // 391

// ---------------- scratch (static device memory; no allocations) ----------------
__device__ int     g_deg[N_NODES];
__device__ float   g_dinv[N_NODES];
__device__ int     g_rowptr[N_NODES + 1];
__device__ int     g_fill[N_NODES];
__device__ int2    g_csr[N_EDGES];               // .x = src, .y = bits of norm weight
__device__ __half2 g_h1h[(size_t)N_NODES * 32];  // GEMM output (gather operand), fp16
__device__ __half2 g_h2h[(size_t)N_NODES * 32];  // agg output (GEMM input), fp16
__device__ int     g_blocksum[SCAN_BLOCKS];
__device__ int     g_blockoff[SCAN_BLOCKS];

// ---------------- preprocessing ----------------
__global__ void k_init_deg() {
    int i = blockIdx.x * blockDim.x + threadIdx.x;
    if (i < N_NODES) g_deg[i] = 1;   // self-loop
}

__global__ void k_hist(const int* __restrict__ ei) {
    int e = blockIdx.x * blockDim.x + threadIdx.x;
    if (e < N_EDGES) {
        int d = ei[N_EDGES + e];
        if ((unsigned)d >= N_NODES) d = 0;
        atomicAdd(&g_deg[d], 1);
    }
}

__global__ void k_blockscan() {
    __shared__ int wsum[8];
    int tid = threadIdx.x;
    int lane = tid & 31;
    int wid = tid >> 5;
    int i = blockIdx.x * 256 + tid;

    int e = 0;
    if (i < N_NODES) {
        int dg = g_deg[i];
        g_dinv[i] = rsqrtf((float)dg);
        e = dg - 1;
    }
    int incl = e;
#pragma unroll
    for (int o = 1; o < 32; o <<= 1) {
        int v = __shfl_up_sync(0xffffffffu, incl, o);
        if (lane >= o) incl += v;
    }
    if (lane == 31) wsum[wid] = incl;
    __syncthreads();
    if (wid == 0) {
        int v = (lane < 8) ? wsum[lane] : 0;
        int s = v;
#pragma unroll
        for (int o = 1; o < 8; o <<= 1) {
            int u = __shfl_up_sync(0xffffffffu, s, o);
            if (lane >= o) s += u;
        }
        if (lane < 8) wsum[lane] = s - v;
    }
    __syncthreads();
    int excl = incl - e + wsum[wid];
    if (i < N_NODES) g_rowptr[i] = excl;
    if (tid == 255) g_blocksum[blockIdx.x] = excl + e;
}

__global__ void k_scanmid() {
    __shared__ int wsum[16];
    int tid = threadIdx.x;
    int lane = tid & 31;
    int wid = tid >> 5;
    int v = (tid < SCAN_BLOCKS) ? g_blocksum[tid] : 0;
    int incl = v;
#pragma unroll
    for (int o = 1; o < 32; o <<= 1) {
        int u = __shfl_up_sync(0xffffffffu, incl, o);
        if (lane >= o) incl += u;
    }
    if (lane == 31) wsum[wid] = incl;
    __syncthreads();
    if (wid == 0) {
        int w = (lane < 16) ? wsum[lane] : 0;
        int s = w;
#pragma unroll
        for (int o = 1; o < 16; o <<= 1) {
            int u = __shfl_up_sync(0xffffffffu, s, o);
            if (lane >= o) s += u;
        }
        if (lane < 16) wsum[lane] = s - w;
    }
    __syncthreads();
    int excl = incl - v + wsum[wid];
    if (tid < SCAN_BLOCKS) g_blockoff[tid] = excl;
    if (tid == SCAN_BLOCKS - 1) g_rowptr[N_NODES] = excl + v;
}

__global__ void k_addoff() {
    int i = blockIdx.x * blockDim.x + threadIdx.x;
    if (i < N_NODES) {
        int v = g_rowptr[i] + g_blockoff[i >> 8];
        g_rowptr[i] = v;
        g_fill[i] = v;
    }
}

__global__ void k_scatter(const int* __restrict__ ei) {
    int e = blockIdx.x * blockDim.x + threadIdx.x;
    if (e < N_EDGES) {
        int s = ei[e];
        int d = ei[N_EDGES + e];
        if ((unsigned)s >= N_NODES) s = 0;
        if ((unsigned)d >= N_NODES) d = 0;
        int pos = atomicAdd(&g_fill[d], 1);
        if ((unsigned)pos < N_EDGES) {
            float w = g_dinv[s] * g_dinv[d];
            g_csr[pos] = make_int2(s, __float_as_int(w));
        }
    }
}

// ---------------- HMMA GEMM: g_h1h[N,64](fp16) = X[N,KDIM] @ W[KDIM,64] ------
// 256 threads (8 warps), tile M=128 x N=64, K chunked by 64.
// Warp w owns rows [w*16, w*16+16) as 1(m) x 4(n) wmma 16x16x16 fragments,
// fp16 in / fp32 accum. B fragments loaded one-at-a-time to cap live regs.
// Smem: As[128][72] fp16 + Bs[64][72] fp16, union'd with Cs[128][68] fp32.
// SRC=0: X = fp32 param (layer 1).  SRC=1: X = g_h2h fp16 (layers 2,3).
template <int KDIM, int SRC>
__global__ void __launch_bounds__(256, 3)
k_gemm_mma(const float* __restrict__ Xp, const float* __restrict__ Wp) {
    constexpr int LDA = 72;   // halves per As/Bs row (144B, 16B-aligned)
    constexpr int LDC = 68;   // floats per Cs row (272B)
    __shared__ __align__(16) char sbuf[128 * LDC * 4];   // 34816 B
    __half* As = (__half*)sbuf;                          // 128*72*2 = 18432
    __half* Bs = (__half*)(sbuf + 128 * LDA * 2);        // 64*72*2  =  9216
    float*  Cs = (float*)sbuf;

    int tid = threadIdx.x;
    int wid = tid >> 5;
    int base = blockIdx.x * 128;
    int m0 = wid * 16;

    wmma::fragment<wmma::accumulator, 16, 16, 16, float> acc[4];
#pragma unroll
    for (int j = 0; j < 4; j++) wmma::fill_fragment(acc[j], 0.f);

    const int NCHUNK = KDIM / 64;
    for (int c = 0; c < NCHUNK; c++) {
        __syncthreads();   // previous chunk fully consumed
        // ---- stage A chunk: rows [base,base+128), k in [c*64, c*64+64) ----
        if (SRC == 0) {
#pragma unroll
            for (int it = 0; it < 4; it++) {
                int idx = tid + 256 * it;      // 0..1023
                int r = idx >> 3;              // row 0..127
                int k8 = idx & 7;              // 8-half segment
                float4 v0 = make_float4(0.f, 0.f, 0.f, 0.f);
                float4 v1 = make_float4(0.f, 0.f, 0.f, 0.f);
                int grow = base + r;
                if (grow < N_NODES) {
                    const float* xr = &Xp[(size_t)grow * KDIM + c * 64 + k8 * 8];
                    v0 = *(const float4*)xr;
                    v1 = *(const float4*)(xr + 4);
                }
                __half2 h[4];
                h[0] = __floats2half2_rn(v0.x, v0.y);
                h[1] = __floats2half2_rn(v0.z, v0.w);
                h[2] = __floats2half2_rn(v1.x, v1.y);
                h[3] = __floats2half2_rn(v1.z, v1.w);
                *(uint4*)&As[r * LDA + k8 * 8] = *(uint4*)h;
            }
        } else {
            const uint4* X = (const uint4*)g_h2h;   // 8 uint4 per 64-half row
#pragma unroll
            for (int it = 0; it < 4; it++) {
                int idx = tid + 256 * it;
                int r = idx >> 3;
                int k8 = idx & 7;
                uint4 v = make_uint4(0u, 0u, 0u, 0u);
                int grow = base + r;
                if (grow < N_NODES) v = X[(size_t)grow * 8 + k8];
                *(uint4*)&As[r * LDA + k8 * 8] = v;
            }
        }
        // ---- stage B chunk: Bs[k][n] = W[c*64+k][n], row-major ----
#pragma unroll
        for (int it = 0; it < 2; it++) {
            int idx = tid + 256 * it;          // 0..511
            int k = idx >> 3;                  // 0..63
            int n8 = idx & 7;
            const float* wr = &Wp[(size_t)(c * 64 + k) * 64 + n8 * 8];
            float4 v0 = *(const float4*)wr;
            float4 v1 = *(const float4*)(wr + 4);
            __half2 h[4];
            h[0] = __floats2half2_rn(v0.x, v0.y);
            h[1] = __floats2half2_rn(v0.z, v0.w);
            h[2] = __floats2half2_rn(v1.x, v1.y);
            h[3] = __floats2half2_rn(v1.z, v1.w);
            *(uint4*)&Bs[k * LDA + n8 * 8] = *(uint4*)h;
        }
        __syncthreads();

        // ---- 4 k-steps of 16 ----
#pragma unroll
        for (int kk = 0; kk < 4; kk++) {
            wmma::fragment<wmma::matrix_a, 16, 16, 16, __half, wmma::row_major> a;
            wmma::load_matrix_sync(a, &As[(m0)*LDA + kk * 16], LDA);
#pragma unroll
            for (int j = 0; j < 4; j++) {
                wmma::fragment<wmma::matrix_b, 16, 16, 16, __half, wmma::row_major> b;
                wmma::load_matrix_sync(b, &Bs[kk * 16 * LDA + j * 16], LDA);
                wmma::mma_sync(acc[j], a, b, acc[j]);
            }
        }
    }

    // ---- epilogue: fragments -> Cs (fp32) -> g_h1h (fp16) ----
    __syncthreads();   // all warps done reading As/Bs (Cs aliases them)
#pragma unroll
    for (int j = 0; j < 4; j++)
        wmma::store_matrix_sync(&Cs[m0 * LDC + j * 16], acc[j], LDC,
                                wmma::mem_row_major);
    __syncthreads();

    // 256 threads, 128 rows: thread t -> row t>>1, half (t&1)
    {
        int r = tid >> 1;
        int half = tid & 1;
        int row = base + r;
        if (row < N_NODES) {
            const float* cr = &Cs[r * LDC + half * 32];
            __half2 h[16];
#pragma unroll
            for (int p = 0; p < 16; p++) {
                float2 f = *(const float2*)&cr[2 * p];
                h[p] = __floats2half2_rn(f.x, f.y);
            }
            uint4* o = (uint4*)&g_h1h[(size_t)row * 32 + half * 16];
#pragma unroll
            for (int q = 0; q < 4; q++) o[q] = ((uint4*)h)[q];
        }
    }
}

// ---------------- Aggregation + epilogue: warp per node ----------------
// OUT[i] = sum_{e: dst=i} w_e * h1h[src_e] + dinv[i]^2 * h1h[i] + bias
// MODE=1: relu + L2-normalize -> g_h2h (fp16).  MODE=0: plain -> OUTp (fp32).
template <int MODE>
__global__ void k_agg(const float* __restrict__ bias, float* __restrict__ OUTp) {
    int gwarp = (blockIdx.x * blockDim.x + threadIdx.x) >> 5;
    int lane = threadIdx.x & 31;
    if (gwarp >= N_NODES) return;
    int i = gwarp;

    float di = g_dinv[i];
    int beg = g_rowptr[i];
    int end = g_rowptr[i + 1];

    const __half2* __restrict__ H = g_h1h;
    float2 hv = __half22float2(H[(size_t)i * 32 + lane]);
    float wself = di * di;
    float a0 = wself * hv.x;
    float a1 = wself * hv.y;

    int j = beg;
    for (; j + 4 <= end; j += 4) {
        int2 e0 = g_csr[j + 0];
        int2 e1 = g_csr[j + 1];
        int2 e2 = g_csr[j + 2];
        int2 e3 = g_csr[j + 3];
        float2 h0 = __half22float2(H[(size_t)e0.x * 32 + lane]);
        float2 h1v = __half22float2(H[(size_t)e1.x * 32 + lane]);
        float2 h2v = __half22float2(H[(size_t)e2.x * 32 + lane]);
        float2 h3 = __half22float2(H[(size_t)e3.x * 32 + lane]);
        a0 += __int_as_float(e0.y) * h0.x;  a1 += __int_as_float(e0.y) * h0.y;
        a0 += __int_as_float(e1.y) * h1v.x; a1 += __int_as_float(e1.y) * h1v.y;
        a0 += __int_as_float(e2.y) * h2v.x; a1 += __int_as_float(e2.y) * h2v.y;
        a0 += __int_as_float(e3.y) * h3.x;  a1 += __int_as_float(e3.y) * h3.y;
    }
    for (; j < end; j++) {
        int2 sw = g_csr[j];
        float w = __int_as_float(sw.y);
        float2 hs = __half22float2(H[(size_t)sw.x * 32 + lane]);
        a0 += w * hs.x;
        a1 += w * hs.y;
    }

    float2 b = ((const float2*)bias)[lane];
    a0 += b.x;
    a1 += b.y;

    if (MODE == 1) {
        a0 = fmaxf(a0, 0.f);
        a1 = fmaxf(a1, 0.f);
        float ss = a0 * a0 + a1 * a1;
#pragma unroll
        for (int o = 16; o; o >>= 1) ss += __shfl_xor_sync(0xffffffffu, ss, o);
        float inv = 1.f / fmaxf(sqrtf(ss), 1e-12f);
        a0 *= inv;
        a1 *= inv;
        g_h2h[(size_t)i * 32 + lane] = __floats2half2_rn(a0, a1);
    } else {
        ((float2*)OUTp)[(size_t)i * 32 + lane] = make_float2(a0, a1);
    }
}

// ---------------- launch ----------------
extern "C" void kernel_launch(void* const* d_in, const int* in_sizes, int n_in,
                              void* d_out, int out_size) {
    const float* x = (const float*)d_in[0];
    const int* ei = (const int*)d_in[1];     // int32 edge_index [2, E]
    const float* W1 = (const float*)d_in[2];
    const float* b1 = (const float*)d_in[3];
    const float* W2 = (const float*)d_in[4];
    const float* b2 = (const float*)d_in[5];
    const float* W3 = (const float*)d_in[6];
    const float* b3 = (const float*)d_in[7];
    float* out = (float*)d_out;

    const int T = 256;
    int gemm_grid = (N_NODES + 127) / 128;
    int agg_grid = (N_NODES * 32 + T - 1) / T;

    // preprocessing with gemm1 at launch index 3 (ncu capture target)
    k_init_deg<<<SCAN_BLOCKS, T>>>();                       // 0
    k_hist<<<(N_EDGES + T - 1) / T, T>>>(ei);               // 1
    k_blockscan<<<SCAN_BLOCKS, T>>>();                      // 2
    k_gemm_mma<256, 0><<<gemm_grid, 256>>>(x, W1);          // 3  <- profiled
    k_scanmid<<<1, 512>>>();                                // 4
    k_addoff<<<SCAN_BLOCKS, T>>>();                         // 5
    k_scatter<<<(N_EDGES + T - 1) / T, T>>>(ei);            // 6

    // layer 1 aggregation
    k_agg<1><<<agg_grid, T>>>(b1, nullptr);                 // 7
    // layer 2
    k_gemm_mma<64, 1><<<gemm_grid, 256>>>(nullptr, W2);     // 8
    k_agg<1><<<agg_grid, T>>>(b2, nullptr);                 // 9
    // layer 3
    k_gemm_mma<64, 1><<<gemm_grid, 256>>>(nullptr, W3);     // 10
    k_agg<0><<<agg_grid, T>>>(b3, out);                     // 11
}